// round 5
// baseline (speedup 1.0000x reference)
#include <cuda_runtime.h>
#include <math.h>

// ---------------- problem constants ----------------
#define S   8
#define T   12
#define H   256
#define F   316
#define B   1024
#define L   48
#define G   1024      // 4*H
#define NB  256       // persistent grid size (256 <= 148 SMs * 2 blocks guaranteed)

// ---------------- scratch (device globals; no allocs allowed) ----------------
__device__ float g_Gin[96l * B * G];           // encoder input gates [s*12+t][b][g]
__device__ float g_enc[(long)T * S * B * H];   // encoder outputs [t][s][b][h]
__device__ float g_k2 [(long)T * S * B * H];   // transformed keys [t][s][b][h]
__device__ float g_hA [S * B * H];
__device__ float g_hB [S * B * H];
__device__ float g_c  [S * B * H];
__device__ float g_inp[L * B];
__device__ float g_outs[(long)L * S * B];
// small precomputed tensors
__device__ float g_M1   [S * H * H];   // Wq^T @ Wk per stream
__device__ float g_u    [S * H];
__device__ float g_wbqk [S * H];
__device__ float g_wvu  [S * H];
__device__ float g_k2b  [S * H];
__device__ float g_cbqk [S];
__device__ float g_cvu  [S];
__device__ float g_c1   [S];
__device__ float g_bqk  [(long)T * S * B];
__device__ float g_vu   [(long)T * S * B];
// grid barrier word: gen<<16 | count
__device__ unsigned g_bar;

__device__ __forceinline__ float sigf(float x) { return 1.f / (1.f + __expf(-x)); }

__device__ __forceinline__ unsigned f2tf(float f) {
    unsigned u;
    asm("cvt.rna.tf32.f32 %0, %1;" : "=r"(u) : "f"(f));
    return u;
}

__device__ __forceinline__ void mma_tf32(float c[4],
    unsigned a0, unsigned a1, unsigned a2, unsigned a3,
    unsigned b0, unsigned b1)
{
    asm volatile(
        "mma.sync.aligned.m16n8k8.row.col.f32.tf32.tf32.f32 "
        "{%0,%1,%2,%3}, {%4,%5,%6,%7}, {%8,%9}, {%0,%1,%2,%3};"
        : "+f"(c[0]), "+f"(c[1]), "+f"(c[2]), "+f"(c[3])
        : "r"(a0), "r"(a1), "r"(a2), "r"(a3), "r"(b0), "r"(b1));
}

// single-word generation grid barrier (all NB blocks guaranteed resident)
__device__ __forceinline__ void grid_bar() {
    __syncthreads();
    if (threadIdx.x == 0) {
        __threadfence();
        unsigned old = atomicAdd(&g_bar, 1u);
        unsigned gen = old >> 16;
        if ((old & 0xffffu) == NB - 1)
            atomicAdd(&g_bar, 0x10000u - NB);   // cnt -= NB, gen += 1
        while ((*(volatile unsigned*)&g_bar) >> 16 == gen) __nanosleep(64);
        __threadfence();
    }
    __syncthreads();
}

// ---------------- prep ----------------
__global__ void prep_kernel(const float* __restrict__ x, const float* __restrict__ tgt) {
    int i = blockIdx.x * blockDim.x + threadIdx.x;
    if (i < S * B * H) { g_hA[i] = 0.f; }
    if (i < L * B) {
        int l = i / B, b = i % B;
        g_inp[i] = (l == 0) ? x[(long)b * 96 * F + 95 * F + 0]
                            : tgt[(long)b * L + (l - 1)];
    }
}

// ---------------- small precomputes (one-time) ----------------
__global__ void pc_a(const float* __restrict__ Wout, const float* __restrict__ Wfcout,
                     const float* __restrict__ Win,  const float* __restrict__ b_in) {
    int t = blockIdx.x * blockDim.x + threadIdx.x;
    if (t >= S * H) return;
    int s = t >> 8, e = t & 255;
    const float* wf2 = Wfcout + s * 2 * H + H;
    const float* Wo  = Wout + (long)s * H * H;
    float u = 0.f;
    for (int o = 0; o < H; o++) u += wf2[o] * Wo[o * H + e];
    g_u[t] = u;
    const float* bq = b_in + s * 3 * H;
    const float* bk = bq + H;
    const float* Wq = Win + (long)s * 3 * H * H;
    const float* Wk = Wq + H * H;
    float wb = 0.f, kb = 0.f;
    for (int e2 = 0; e2 < H; e2++) {
        wb += bq[e2] * Wk[e2 * H + e];
        kb += Wq[e2 * H + e] * bk[e2];
    }
    g_wbqk[t] = wb;
    g_k2b[t]  = kb;
}

__global__ void pc_b(const float* __restrict__ Win, const float* __restrict__ b_in,
                     const float* __restrict__ Wfcout, const float* __restrict__ b_fcout,
                     const float* __restrict__ b_out) {
    int t = blockIdx.x * blockDim.x + threadIdx.x;
    if (t >= S * H) return;
    int s = t >> 8, h = t & 255;
    const float* Wv = Win + (long)s * 3 * H * H + 2 * H * H;
    float wv = 0.f;
    for (int e = 0; e < H; e++) wv += g_u[s * H + e] * Wv[e * H + h];
    g_wvu[t] = wv;
    if (h == 0) {
        const float* bq = b_in + s * 3 * H;
        const float* bk = bq + H;
        const float* bv = bq + 2 * H;
        const float* wf2 = Wfcout + s * 2 * H + H;
        const float* bo  = b_out + s * H;
        float cvu = 0.f, cb = 0.f, c1 = 0.f;
        for (int e = 0; e < H; e++) {
            cvu += g_u[s * H + e] * bv[e];
            cb  += bq[e] * bk[e];
            c1  += wf2[e] * bo[e];
        }
        g_cvu[s]  = cvu;
        g_cbqk[s] = cb;
        g_c1[s]   = c1 + b_fcout[s];
    }
}

__global__ void pc_m1(const float* __restrict__ Win) {
    __shared__ float tq[16][17];
    __shared__ float tk[16][17];
    int s = blockIdx.z;
    const float* Wq = Win + (long)s * 3 * H * H;
    const float* Wk = Wq + H * H;
    int tyy = threadIdx.y, txx = threadIdx.x;
    int hq = blockIdx.y * 16 + tyy;
    int hk = blockIdx.x * 16 + txx;
    float acc = 0.f;
    for (int e0 = 0; e0 < H; e0 += 16) {
        tq[tyy][txx] = Wq[(e0 + tyy) * H + blockIdx.y * 16 + txx];
        tk[tyy][txx] = Wk[(e0 + tyy) * H + hk];
        __syncthreads();
#pragma unroll
        for (int ee = 0; ee < 16; ee++)
            acc = fmaf(tq[ee][tyy], tk[ee][txx], acc);
        __syncthreads();
    }
    g_M1[(long)s * H * H + hq * H + hk] = acc;
}

// ================= generic tf32 tensor-core GEMM (Gin, k2) =================
__global__ void __launch_bounds__(256) gemm_tc(
    const float* __restrict__ Ag, long sAz, int lda,
    const float* __restrict__ Wg, long sWz, int ldw,
    const float* __restrict__ b1, const float* __restrict__ b2, long sBz,
    float* __restrict__ C, long sCz, int ldc,
    int K, int wdiv)
{
    __shared__ unsigned As[2][128 * 20];
    __shared__ unsigned Ws[2][128 * 20];

    const int z  = blockIdx.z;
    const int wi = (z / wdiv) & 7;
    const int m0 = blockIdx.y * 128;
    const int n0 = blockIdx.x * 128;

    const float* Ap = Ag + (long)z * sAz + (long)m0 * lda;
    const float* Wp = Wg + (long)wi * sWz + (long)n0 * ldw;

    const int t = threadIdx.x;
    const int w = t >> 5, lane = t & 31;
    const int lq = lane >> 2, lr = lane & 3;
    const int wm = w & 3, wn = w >> 2;

    float4 pa[2], pw[2];

    auto ld = [&](int c) {
        int k0 = c * 16;
#pragma unroll
        for (int p = 0; p < 2; p++) {
            int i = t + 256 * p;
            int row = i >> 2, k4 = i & 3;
            int k = k0 + k4 * 4;
            if (k < K) {
                pa[p] = *(const float4*)(Ap + (long)row * lda + k);
                pw[p] = *(const float4*)(Wp + (long)row * ldw + k);
            } else {
                pa[p] = make_float4(0.f, 0.f, 0.f, 0.f);
                pw[p] = make_float4(0.f, 0.f, 0.f, 0.f);
            }
        }
    };
    auto st = [&](int bf) {
#pragma unroll
        for (int p = 0; p < 2; p++) {
            int i = t + 256 * p;
            int row = i >> 2, k4 = i & 3;
            uint4 ua = make_uint4(f2tf(pa[p].x), f2tf(pa[p].y), f2tf(pa[p].z), f2tf(pa[p].w));
            uint4 uw = make_uint4(f2tf(pw[p].x), f2tf(pw[p].y), f2tf(pw[p].z), f2tf(pw[p].w));
            *(uint4*)&As[bf][row * 20 + k4 * 4] = ua;
            *(uint4*)&Ws[bf][row * 20 + k4 * 4] = uw;
        }
    };

    float acc[2][8][4];
#pragma unroll
    for (int mt = 0; mt < 2; mt++)
#pragma unroll
        for (int nt = 0; nt < 8; nt++)
#pragma unroll
            for (int v = 0; v < 4; v++) acc[mt][nt][v] = 0.f;

    const int NC = (K + 15) / 16;
    ld(0); st(0);
    __syncthreads();

    for (int c = 0; c < NC; c++) {
        int cur = c & 1;
        if (c + 1 < NC) ld(c + 1);
#pragma unroll
        for (int k8s = 0; k8s < 2; k8s++) {
            int kb = k8s * 8;
            unsigned a[2][4];
#pragma unroll
            for (int mt = 0; mt < 2; mt++) {
                int r = wm * 32 + mt * 16 + lq;
                a[mt][0] = As[cur][r * 20 + kb + lr];
                a[mt][1] = As[cur][(r + 8) * 20 + kb + lr];
                a[mt][2] = As[cur][r * 20 + kb + lr + 4];
                a[mt][3] = As[cur][(r + 8) * 20 + kb + lr + 4];
            }
#pragma unroll
            for (int nt = 0; nt < 8; nt++) {
                int rn = wn * 64 + nt * 8 + lq;
                unsigned bb0 = Ws[cur][rn * 20 + kb + lr];
                unsigned bb1 = Ws[cur][rn * 20 + kb + lr + 4];
#pragma unroll
                for (int mt = 0; mt < 2; mt++)
                    mma_tf32(acc[mt][nt], a[mt][0], a[mt][1], a[mt][2], a[mt][3], bb0, bb1);
            }
        }
        if (c + 1 < NC) st(cur ^ 1);
        __syncthreads();
    }

    C += (long)z * sCz;
#pragma unroll
    for (int mt = 0; mt < 2; mt++) {
#pragma unroll
        for (int nt = 0; nt < 8; nt++) {
#pragma unroll
            for (int rh = 0; rh < 2; rh++) {
                int m = m0 + wm * 32 + mt * 16 + lq + rh * 8;
                int n = n0 + wn * 64 + nt * 8 + lr * 2;
                float v0 = acc[mt][nt][rh * 2];
                float v1 = acc[mt][nt][rh * 2 + 1];
                if (b1) { v0 += b1[(long)wi * sBz + n]; v1 += b1[(long)wi * sBz + n + 1]; }
                if (b2) { v0 += b2[(long)wi * sBz + n]; v1 += b2[(long)wi * sBz + n + 1]; }
                *(float2*)&C[(long)m * ldc + n] = make_float2(v0, v1);
            }
        }
    }
}

// ================= persistent recurrence kernel =================
// NB=256 blocks x 256 thr, __launch_bounds__(256,2) => regs<=128, 2 blocks/SM
// guaranteed (smem 30KB/block). All blocks resident -> grid barrier safe.
// Block owns 128 b-rows x 64 j (4 tiles of 128 x [4g x 16 j] run sequentially).
// c-state in registers for the whole launch.
// Smem weight row r (and MMA n-col) map: q=(r>>3)&3, jj=(r&7)+((r>>5)<<3).
template <int DEC>
__global__ void __launch_bounds__(256, 2) persist_k(
    const float* __restrict__ Whh,
    const float* __restrict__ b1,      // dec: b_ih_d
    const float* __restrict__ b2,      // dec: b_hh_d
    const float* __restrict__ cvec,    // dec: W_ih_d as [S][G]
    const float* __restrict__ Wfcout)  // dec
{
    __shared__ unsigned As[2][128 * 20];
    __shared__ unsigned Ws[2][64 * 20];

    const int bid   = blockIdx.x;
    const int s     = bid >> 5;
    const int m0    = ((bid >> 2) & 7) * 128;
    const int jbase = (bid & 3) * 64;

    const int t = threadIdx.x;
    const int w = t >> 5, lane = t & 31;
    const int lq = lane >> 2, lr = lane & 3;
    const int wm = w & 3, wn = w >> 2;   // 4 m-warps x 2 n-warps

    const float* Wp = Whh + (long)s * (4 * H * H);

    // this thread's j pair within a tile: jj, jj+1
    const int jj = wn * 8 + lr * 2;

    // c-state: creg[tile p][mt*2+rh][d]
    float creg[4][4][2];
    if (DEC) {
#pragma unroll
        for (int p = 0; p < 4; p++) {
            int j = jbase + p * 16 + jj;
#pragma unroll
            for (int mt = 0; mt < 2; mt++)
#pragma unroll
                for (int rh = 0; rh < 2; rh++) {
                    int b_row = m0 + wm * 32 + mt * 16 + lq + rh * 8;
                    float2 cc = *(const float2*)&g_c[((long)s * B + b_row) * H + j];
                    creg[p][mt * 2 + rh][0] = cc.x;
                    creg[p][mt * 2 + rh][1] = cc.y;
                }
        }
    } else {
#pragma unroll
        for (int p = 0; p < 4; p++)
#pragma unroll
            for (int i = 0; i < 4; i++) { creg[p][i][0] = 0.f; creg[p][i][1] = 0.f; }
    }

    const int NSTEP = DEC ? (L + 1) : T;

#pragma unroll 1
    for (int it = 0; it < NSTEP; it++) {
        if (!DEC || it < L) {
            const float* Ap;
            if (DEC) {
                Ap = (it == 0) ? (g_enc + (((long)11 * S + s) * B + m0) * H)
                               : ((((it - 1) & 1) ? g_hB : g_hA) + ((long)s * B + m0) * H);
            } else {
                Ap = (it == 0) ? (g_hA + ((long)s * B + m0) * H)
                               : (g_enc + (((long)(it - 1) * S + s) * B + m0) * H);
            }
            float* hb = DEC ? ((it & 1) ? g_hB : g_hA) : nullptr;

#pragma unroll 1
            for (int p = 0; p < 4; p++) {
                const int j0 = jbase + p * 16;

                float4 pa[2], pw;
                auto ld = [&](int c) {
                    int k0 = c * 16;
#pragma unroll
                    for (int pp = 0; pp < 2; pp++) {
                        int i = t + 256 * pp;
                        int row = i >> 2, k4 = i & 3;
                        pa[pp] = *(const float4*)(Ap + (long)row * H + k0 + k4 * 4);
                    }
                    {
                        int r = t >> 2, k4 = t & 3;
                        int grow = ((r >> 3) & 3) * H + j0 + (r & 7) + ((r >> 5) << 3);
                        pw = *(const float4*)(Wp + (long)grow * H + k0 + k4 * 4);
                    }
                };
                auto st = [&](int bf) {
#pragma unroll
                    for (int pp = 0; pp < 2; pp++) {
                        int i = t + 256 * pp;
                        int row = i >> 2, k4 = i & 3;
                        uint4 ua = make_uint4(f2tf(pa[pp].x), f2tf(pa[pp].y), f2tf(pa[pp].z), f2tf(pa[pp].w));
                        *(uint4*)&As[bf][row * 20 + k4 * 4] = ua;
                    }
                    {
                        int r = t >> 2, k4 = t & 3;
                        uint4 uw = make_uint4(f2tf(pw.x), f2tf(pw.y), f2tf(pw.z), f2tf(pw.w));
                        *(uint4*)&Ws[bf][r * 20 + k4 * 4] = uw;
                    }
                };

                float acc[2][4][4];
#pragma unroll
                for (int mt = 0; mt < 2; mt++)
#pragma unroll
                    for (int nt = 0; nt < 4; nt++)
#pragma unroll
                        for (int v = 0; v < 4; v++) acc[mt][nt][v] = 0.f;

                ld(0); st(0);
                __syncthreads();

#pragma unroll 1
                for (int c = 0; c < 16; c++) {
                    int cur = c & 1;
                    if (c < 15) ld(c + 1);
#pragma unroll
                    for (int k8s = 0; k8s < 2; k8s++) {
                        int kb = k8s * 8;
                        unsigned a[2][4];
#pragma unroll
                        for (int mt = 0; mt < 2; mt++) {
                            int r = wm * 32 + mt * 16 + lq;
                            a[mt][0] = As[cur][r * 20 + kb + lr];
                            a[mt][1] = As[cur][(r + 8) * 20 + kb + lr];
                            a[mt][2] = As[cur][r * 20 + kb + lr + 4];
                            a[mt][3] = As[cur][(r + 8) * 20 + kb + lr + 4];
                        }
#pragma unroll
                        for (int nt = 0; nt < 4; nt++) {
                            int rn = wn * 32 + nt * 8 + lq;
                            unsigned bb0 = Ws[cur][rn * 20 + kb + lr];
                            unsigned bb1 = Ws[cur][rn * 20 + kb + lr + 4];
#pragma unroll
                            for (int mt = 0; mt < 2; mt++)
                                mma_tf32(acc[mt][nt], a[mt][0], a[mt][1], a[mt][2], a[mt][3], bb0, bb1);
                        }
                    }
                    if (c < 15) st(cur ^ 1);
                    __syncthreads();
                }

                // ---- epilogue: extras + LSTM (c in regs); acc nt == gate q ----
                const int j = j0 + jj;
#pragma unroll
                for (int mt = 0; mt < 2; mt++) {
#pragma unroll
                    for (int rh = 0; rh < 2; rh++) {
                        int b_row = m0 + wm * 32 + mt * 16 + lq + rh * 8;
                        float rv = DEC ? g_inp[it * B + b_row] : 0.f;
                        float gate[4][2];
#pragma unroll
                        for (int q = 0; q < 4; q++) {
                            float v0 = acc[mt][q][rh * 2];
                            float v1 = acc[mt][q][rh * 2 + 1];
                            int gg = q * H + j;
                            if (DEC) {
                                float2 x1 = *(const float2*)&b1[s * G + gg];
                                float2 x2 = *(const float2*)&b2[s * G + gg];
                                float2 xc = *(const float2*)&cvec[s * G + gg];
                                v0 += x1.x + x2.x + rv * xc.x;
                                v1 += x1.y + x2.y + rv * xc.y;
                            } else {
                                float2 xa = *(const float2*)&g_Gin[(((long)s * T + it) * B + b_row) * G + gg];
                                v0 += xa.x; v1 += xa.y;
                            }
                            gate[q][0] = v0; gate[q][1] = v1;
                        }
                        int ci = mt * 2 + rh;
                        float hn[2];
#pragma unroll
                        for (int dd = 0; dd < 2; dd++) {
                            float c_ = sigf(gate[1][dd]) * creg[p][ci][dd]
                                     + sigf(gate[0][dd]) * tanhf(gate[2][dd]);
                            creg[p][ci][dd] = c_;
                            hn[dd] = sigf(gate[3][dd]) * tanhf(c_);
                        }
                        if (DEC)
                            *(float2*)&hb[((long)s * B + b_row) * H + j] = make_float2(hn[0], hn[1]);
                        else
                            *(float2*)&g_enc[(((long)it * S + s) * B + b_row) * H + j] = make_float2(hn[0], hn[1]);
                    }
                }
            }
        }

        // ---- fused attention for step it-1 (decoder) ----
        if (DEC && it > 0) {
            int lstep = it - 1;
            const float* hbp = (lstep & 1) ? g_hB : g_hA;
            int gw = bid * 8 + w;            // 2048 warps total
#pragma unroll 1
            for (int rep = 0; rep < 4; rep++) {
                int sb = gw + rep * 2048;    // s*B + b
                int ss = sb >> 10;
                const float* hp = hbp + (long)sb * H;
                float4 h0 = *(const float4*)&hp[lane * 4];
                float4 h1 = *(const float4*)&hp[128 + lane * 4];
                const float* wf = Wfcout + ss * 2 * H;
                float4 w0 = *(const float4*)&wf[lane * 4];
                float4 w1 = *(const float4*)&wf[128 + lane * 4];

                float red[T + 1];
                red[T] = h0.x * w0.x + h0.y * w0.y + h0.z * w0.z + h0.w * w0.w
                       + h1.x * w1.x + h1.y * w1.y + h1.z * w1.z + h1.w * w1.w;
#pragma unroll
                for (int tt = 0; tt < T; tt++) {
                    const float* kp = g_k2 + ((long)tt * S * B + sb) * H;
                    float4 k0 = *(const float4*)&kp[lane * 4];
                    float4 k1 = *(const float4*)&kp[128 + lane * 4];
                    red[tt] = h0.x * k0.x + h0.y * k0.y + h0.z * k0.z + h0.w * k0.w
                            + h1.x * k1.x + h1.y * k1.y + h1.z * k1.z + h1.w * k1.w;
                }
#pragma unroll
                for (int r = 0; r < T + 1; r++) {
                    float v = red[r];
#pragma unroll
                    for (int off = 16; off; off >>= 1) v += __shfl_xor_sync(0xffffffffu, v, off);
                    red[r] = v;
                }
                float sc[T];
                float mx = -1e30f;
#pragma unroll
                for (int tt = 0; tt < T; tt++) {
                    float v = (red[tt] + g_bqk[(long)tt * S * B + sb]) * 0.0625f;
                    sc[tt] = v;
                    mx = fmaxf(mx, v);
                }
                float sum = 0.f;
#pragma unroll
                for (int tt = 0; tt < T; tt++) { sc[tt] = __expf(sc[tt] - mx); sum += sc[tt]; }
                float inv = 1.f / sum;
                float ctxdot = 0.f;
#pragma unroll
                for (int tt = 0; tt < T; tt++)
                    ctxdot = fmaf(sc[tt] * inv, g_vu[(long)tt * S * B + sb], ctxdot);
                if (lane == 0)
                    g_outs[(long)lstep * S * B + sb] = red[T] + ctxdot + g_c1[ss];
            }
        }

        if (it + 1 < NSTEP) grid_bar();
    }

    // encoder: hand c-state to the decoder launch
    if (!DEC) {
#pragma unroll
        for (int p = 0; p < 4; p++) {
            int j = jbase + p * 16 + jj;
#pragma unroll
            for (int mt = 0; mt < 2; mt++)
#pragma unroll
                for (int rh = 0; rh < 2; rh++) {
                    int b_row = m0 + wm * 32 + mt * 16 + lq + rh * 8;
                    *(float2*)&g_c[((long)s * B + b_row) * H + j] =
                        make_float2(creg[p][mt * 2 + rh][0], creg[p][mt * 2 + rh][1]);
                }
        }
    }
}

// ---------------- per-(t,s,b) scalars ----------------
__global__ void pc_scal_kernel() {
    int gtid = blockIdx.x * blockDim.x + threadIdx.x;
    int warp = gtid >> 5;
    int lane = threadIdx.x & 31;
    if (warp >= T * S * B) return;
    int s = (warp >> 10) & 7;

    const float* ep = g_enc + (long)warp * H;
    const float* wb = g_wbqk + s * H;
    const float* wv = g_wvu + s * H;
    float db = 0.f, dv = 0.f;
#pragma unroll
    for (int u = 0; u < 2; u++) {
        int e = lane * 4 + u * 128;
        float4 ev = *(const float4*)&ep[e];
        float4 b4 = *(const float4*)&wb[e];
        float4 v4 = *(const float4*)&wv[e];
        db += ev.x * b4.x + ev.y * b4.y + ev.z * b4.z + ev.w * b4.w;
        dv += ev.x * v4.x + ev.y * v4.y + ev.z * v4.z + ev.w * v4.w;
    }
#pragma unroll
    for (int off = 16; off; off >>= 1) {
        db += __shfl_xor_sync(0xffffffffu, db, off);
        dv += __shfl_xor_sync(0xffffffffu, dv, off);
    }
    if (lane == 0) {
        g_bqk[warp] = db + g_cbqk[s];
        g_vu[warp]  = dv + g_cvu[s];
    }
}

// ---------------- final 8->1 mix ----------------
__global__ void final_kernel(const float* __restrict__ Wfc, const float* __restrict__ bfc,
                             float* __restrict__ out) {
    int i = blockIdx.x * blockDim.x + threadIdx.x;
    if (i >= B * L) return;
    int b = i / L, l = i % L;
    float acc = bfc[0];
#pragma unroll
    for (int s = 0; s < S; s++)
        acc += g_outs[(long)l * S * B + (long)s * B + b] * Wfc[s];
    out[i] = acc;
}

// ---------------- host launch ----------------
extern "C" void kernel_launch(void* const* d_in, const int* in_sizes, int n_in,
                              void* d_out, int out_size) {
    const float* x       = (const float*)d_in[0];
    const float* tgt     = (const float*)d_in[1];
    const float* W_ih_e  = (const float*)d_in[2];
    const float* W_hh_e  = (const float*)d_in[3];
    const float* b_ih_e  = (const float*)d_in[4];
    const float* b_hh_e  = (const float*)d_in[5];
    const float* W_ih_d  = (const float*)d_in[6];
    const float* W_hh_d  = (const float*)d_in[7];
    const float* b_ih_d  = (const float*)d_in[8];
    const float* b_hh_d  = (const float*)d_in[9];
    const float* W_in    = (const float*)d_in[10];
    const float* b_in    = (const float*)d_in[11];
    const float* W_out   = (const float*)d_in[12];
    const float* b_out   = (const float*)d_in[13];
    const float* W_fcout = (const float*)d_in[14];
    const float* b_fcout = (const float*)d_in[15];
    const float* W_fc    = (const float*)d_in[16];
    const float* b_fc    = (const float*)d_in[17];
    float* out = (float*)d_out;

    float *Gin, *enc, *k2, *M1, *k2b;
    cudaGetSymbolAddress((void**)&Gin, g_Gin);
    cudaGetSymbolAddress((void**)&enc, g_enc);
    cudaGetSymbolAddress((void**)&k2,  g_k2);
    cudaGetSymbolAddress((void**)&M1,  g_M1);
    cudaGetSymbolAddress((void**)&k2b, g_k2b);

    prep_kernel<<<(S * B * H + 255) / 256, 256>>>(x, tgt);
    pc_a<<<(S * H + 255) / 256, 256>>>(W_out, W_fcout, W_in, b_in);
    pc_b<<<(S * H + 255) / 256, 256>>>(W_in, b_in, W_fcout, b_fcout, b_out);
    pc_m1<<<dim3(16, 16, 8), dim3(16, 16)>>>(W_in);

    // 1) encoder input projections (biases folded): Gin[z=s*12+t][b][g]
    gemm_tc<<<dim3(G / 128, B / 128, 96), 256>>>(
        x, (long)F, 96 * F,
        W_ih_e, (long)G * F, F,
        b_ih_e, b_hh_e, G,
        Gin, (long)B * G, G, F, 12);

    // 2) persistent encoder (12 steps, 1 launch)
    persist_k<0><<<NB, 256>>>(W_hh_e, nullptr, nullptr, nullptr, nullptr);

    // 3) per-key scalars + transformed keys
    pc_scal_kernel<<<(T * S * B * 32 + 255) / 256, 256>>>();
    gemm_tc<<<dim3(H / 128, B / 128, T * S), 256>>>(
        enc, (long)B * H, H,
        M1, (long)H * H, H,
        k2b, nullptr, H,
        k2, (long)B * H, H, H, 1);

    // 4) persistent decoder (48 steps + fused attention, 1 launch)
    persist_k<1><<<NB, 256>>>(W_hh_d, b_ih_d, b_hh_d, W_ih_d, W_fcout);

    // 5) final mix
    final_kernel<<<(B * L + 255) / 256, 256>>>(W_fc, b_fc, out);
}

// round 6
// speedup vs baseline: 1.1490x; 1.1490x over previous
#include <cuda_runtime.h>
#include <math.h>

// ---------------- problem constants ----------------
#define S   8
#define T   12
#define H   256
#define F   316
#define B   1024
#define L   48
#define G   1024      // 4*H

// ---------------- scratch (device globals; no allocs allowed) ----------------
__device__ float g_Gin[96l * B * G];           // encoder input gates [s*12+t][b][g]
__device__ float g_enc[(long)T * S * B * H];   // encoder outputs [t][s][b][h]
__device__ float g_k2 [(long)T * S * B * H];   // transformed keys [t][s][b][h]
__device__ float g_hA [S * B * H];
__device__ float g_hB [S * B * H];
__device__ float g_c  [S * B * H];
__device__ float g_inp[L * B];
__device__ float g_outs[(long)L * S * B];
// small precomputed tensors
__device__ float g_M1   [S * H * H];   // Wq^T @ Wk per stream
__device__ float g_u    [S * H];
__device__ float g_wbqk [S * H];
__device__ float g_wvu  [S * H];
__device__ float g_k2b  [S * H];
__device__ float g_cbqk [S];
__device__ float g_cvu  [S];
__device__ float g_c1   [S];
__device__ float g_bqk  [(long)T * S * B];
__device__ float g_vu   [(long)T * S * B];

__device__ __forceinline__ float sigf(float x) { return 1.f / (1.f + __expf(-x)); }

__device__ __forceinline__ unsigned f2tf(float f) {
    unsigned u;
    asm("cvt.rna.tf32.f32 %0, %1;" : "=r"(u) : "f"(f));
    return u;
}

__device__ __forceinline__ void mma_tf32(float c[4],
    unsigned a0, unsigned a1, unsigned a2, unsigned a3,
    unsigned b0, unsigned b1)
{
    asm volatile(
        "mma.sync.aligned.m16n8k8.row.col.f32.tf32.tf32.f32 "
        "{%0,%1,%2,%3}, {%4,%5,%6,%7}, {%8,%9}, {%0,%1,%2,%3};"
        : "+f"(c[0]), "+f"(c[1]), "+f"(c[2]), "+f"(c[3])
        : "r"(a0), "r"(a1), "r"(a2), "r"(a3), "r"(b0), "r"(b1));
}

// ---------------- prep ----------------
__global__ void prep_kernel(const float* __restrict__ x, const float* __restrict__ tgt) {
    int i = blockIdx.x * blockDim.x + threadIdx.x;
    if (i < S * B * H) { g_hA[i] = 0.f; g_c[i] = 0.f; }
    if (i < L * B) {
        int l = i / B, b = i % B;
        g_inp[i] = (l == 0) ? x[(long)b * 96 * F + 95 * F + 0]
                            : tgt[(long)b * L + (l - 1)];
    }
}

// ---------------- small precomputes (one-time) ----------------
__global__ void pc_a(const float* __restrict__ Wout, const float* __restrict__ Wfcout,
                     const float* __restrict__ Win,  const float* __restrict__ b_in) {
    int t = blockIdx.x * blockDim.x + threadIdx.x;
    if (t >= S * H) return;
    int s = t >> 8, e = t & 255;
    const float* wf2 = Wfcout + s * 2 * H + H;
    const float* Wo  = Wout + (long)s * H * H;
    float u = 0.f;
    for (int o = 0; o < H; o++) u += wf2[o] * Wo[o * H + e];
    g_u[t] = u;
    const float* bq = b_in + s * 3 * H;
    const float* bk = bq + H;
    const float* Wq = Win + (long)s * 3 * H * H;
    const float* Wk = Wq + H * H;
    float wb = 0.f, kb = 0.f;
    for (int e2 = 0; e2 < H; e2++) {
        wb += bq[e2] * Wk[e2 * H + e];
        kb += Wq[e2 * H + e] * bk[e2];
    }
    g_wbqk[t] = wb;
    g_k2b[t]  = kb;
}

__global__ void pc_b(const float* __restrict__ Win, const float* __restrict__ b_in,
                     const float* __restrict__ Wfcout, const float* __restrict__ b_fcout,
                     const float* __restrict__ b_out) {
    int t = blockIdx.x * blockDim.x + threadIdx.x;
    if (t >= S * H) return;
    int s = t >> 8, h = t & 255;
    const float* Wv = Win + (long)s * 3 * H * H + 2 * H * H;
    float wv = 0.f;
    for (int e = 0; e < H; e++) wv += g_u[s * H + e] * Wv[e * H + h];
    g_wvu[t] = wv;
    if (h == 0) {
        const float* bq = b_in + s * 3 * H;
        const float* bk = bq + H;
        const float* bv = bq + 2 * H;
        const float* wf2 = Wfcout + s * 2 * H + H;
        const float* bo  = b_out + s * H;
        float cvu = 0.f, cb = 0.f, c1 = 0.f;
        for (int e = 0; e < H; e++) {
            cvu += g_u[s * H + e] * bv[e];
            cb  += bq[e] * bk[e];
            c1  += wf2[e] * bo[e];
        }
        g_cvu[s]  = cvu;
        g_cbqk[s] = cb;
        g_c1[s]   = c1 + b_fcout[s];
    }
}

__global__ void pc_m1(const float* __restrict__ Win) {
    __shared__ float tq[16][17];
    __shared__ float tk[16][17];
    int s = blockIdx.z;
    const float* Wq = Win + (long)s * 3 * H * H;
    const float* Wk = Wq + H * H;
    int tyy = threadIdx.y, txx = threadIdx.x;
    int hq = blockIdx.y * 16 + tyy;
    int hk = blockIdx.x * 16 + txx;
    float acc = 0.f;
    for (int e0 = 0; e0 < H; e0 += 16) {
        tq[tyy][txx] = Wq[(e0 + tyy) * H + blockIdx.y * 16 + txx];
        tk[tyy][txx] = Wk[(e0 + tyy) * H + hk];
        __syncthreads();
#pragma unroll
        for (int ee = 0; ee < 16; ee++)
            acc = fmaf(tq[ee][tyy], tk[ee][txx], acc);
        __syncthreads();
    }
    g_M1[(long)s * H * H + hq * H + hk] = acc;
}

// ================= generic tf32 tensor-core GEMM (Gin, k2) =================
__global__ void __launch_bounds__(256) gemm_tc(
    const float* __restrict__ Ag, long sAz, int lda,
    const float* __restrict__ Wg, long sWz, int ldw,
    const float* __restrict__ b1, const float* __restrict__ b2, long sBz,
    float* __restrict__ C, long sCz, int ldc,
    int K, int wdiv)
{
    __shared__ unsigned As[2][128 * 20];
    __shared__ unsigned Ws[2][128 * 20];

    const int z  = blockIdx.z;
    const int wi = (z / wdiv) & 7;
    const int m0 = blockIdx.y * 128;
    const int n0 = blockIdx.x * 128;

    const float* Ap = Ag + (long)z * sAz + (long)m0 * lda;
    const float* Wp = Wg + (long)wi * sWz + (long)n0 * ldw;

    const int t = threadIdx.x;
    const int w = t >> 5, lane = t & 31;
    const int lq = lane >> 2, lr = lane & 3;
    const int wm = w & 3, wn = w >> 2;

    float4 pa[2], pw[2];

    auto ld = [&](int c) {
        int k0 = c * 16;
#pragma unroll
        for (int p = 0; p < 2; p++) {
            int i = t + 256 * p;
            int row = i >> 2, k4 = i & 3;
            int k = k0 + k4 * 4;
            if (k < K) {
                pa[p] = *(const float4*)(Ap + (long)row * lda + k);
                pw[p] = *(const float4*)(Wp + (long)row * ldw + k);
            } else {
                pa[p] = make_float4(0.f, 0.f, 0.f, 0.f);
                pw[p] = make_float4(0.f, 0.f, 0.f, 0.f);
            }
        }
    };
    auto st = [&](int bf) {
#pragma unroll
        for (int p = 0; p < 2; p++) {
            int i = t + 256 * p;
            int row = i >> 2, k4 = i & 3;
            uint4 ua = make_uint4(f2tf(pa[p].x), f2tf(pa[p].y), f2tf(pa[p].z), f2tf(pa[p].w));
            uint4 uw = make_uint4(f2tf(pw[p].x), f2tf(pw[p].y), f2tf(pw[p].z), f2tf(pw[p].w));
            *(uint4*)&As[bf][row * 20 + k4 * 4] = ua;
            *(uint4*)&Ws[bf][row * 20 + k4 * 4] = uw;
        }
    };

    float acc[2][8][4];
#pragma unroll
    for (int mt = 0; mt < 2; mt++)
#pragma unroll
        for (int nt = 0; nt < 8; nt++)
#pragma unroll
            for (int v = 0; v < 4; v++) acc[mt][nt][v] = 0.f;

    const int NC = (K + 15) / 16;
    ld(0); st(0);
    __syncthreads();

    for (int c = 0; c < NC; c++) {
        int cur = c & 1;
        if (c + 1 < NC) ld(c + 1);
#pragma unroll
        for (int k8s = 0; k8s < 2; k8s++) {
            int kb = k8s * 8;
            unsigned a[2][4];
#pragma unroll
            for (int mt = 0; mt < 2; mt++) {
                int r = wm * 32 + mt * 16 + lq;
                a[mt][0] = As[cur][r * 20 + kb + lr];
                a[mt][1] = As[cur][(r + 8) * 20 + kb + lr];
                a[mt][2] = As[cur][r * 20 + kb + lr + 4];
                a[mt][3] = As[cur][(r + 8) * 20 + kb + lr + 4];
            }
#pragma unroll
            for (int nt = 0; nt < 8; nt++) {
                int rn = wn * 64 + nt * 8 + lq;
                unsigned bb0 = Ws[cur][rn * 20 + kb + lr];
                unsigned bb1 = Ws[cur][rn * 20 + kb + lr + 4];
#pragma unroll
                for (int mt = 0; mt < 2; mt++)
                    mma_tf32(acc[mt][nt], a[mt][0], a[mt][1], a[mt][2], a[mt][3], bb0, bb1);
            }
        }
        if (c + 1 < NC) st(cur ^ 1);
        __syncthreads();
    }

    C += (long)z * sCz;
#pragma unroll
    for (int mt = 0; mt < 2; mt++) {
#pragma unroll
        for (int nt = 0; nt < 8; nt++) {
#pragma unroll
            for (int rh = 0; rh < 2; rh++) {
                int m = m0 + wm * 32 + mt * 16 + lq + rh * 8;
                int n = n0 + wn * 64 + nt * 8 + lr * 2;
                float v0 = acc[mt][nt][rh * 2];
                float v1 = acc[mt][nt][rh * 2 + 1];
                if (b1) { v0 += b1[(long)wi * sBz + n]; v1 += b1[(long)wi * sBz + n + 1]; }
                if (b2) { v0 += b2[(long)wi * sBz + n]; v1 += b2[(long)wi * sBz + n + 1]; }
                *(float2*)&C[(long)m * ldc + n] = make_float2(v0, v1);
            }
        }
    }
}

// ================= fused step kernel: gates GEMM + LSTM (+ prev-step attn) ====
// 256 thr / 8 warps, tile 128 b-rows x 128 n (4 gates x 32 j), K=256.
// Weight smem row r (= MMA n-col): gate q=(r>>3)&3, jj=(r&7)+((r>>5)<<3),
// global W row = q*H + j0 + jj. Each thread's accumulators then hold all 4
// gates for its (b, j) pairs -> LSTM in epilogue, c-state via gmem.
// DEC: gates extras = b1+b2+inp[it]*cvec; attention for step lstep (if >=0)
// reads hin (= h(lstep)) and writes g_outs[lstep].
template <int DEC>
__global__ void __launch_bounds__(256, 2) step_k(
    const float* __restrict__ hin, float* __restrict__ hout,
    const float* __restrict__ Whh,
    const float* __restrict__ b1, const float* __restrict__ b2,
    const float* __restrict__ cvec,
    const float* __restrict__ add, long sAddz,
    const float* __restrict__ Wfcout,
    int itstep, int lstep)
{
    __shared__ unsigned As[2][128 * 20];
    __shared__ unsigned Ws[2][128 * 20];

    const int s  = blockIdx.z;
    const int m0 = blockIdx.y * 128;
    const int j0 = blockIdx.x * 32;

    const float* Ap = hin + ((long)s * B + m0) * H;
    const float* Wp = Whh + (long)s * (4 * H * H);

    const int t = threadIdx.x;
    const int w = t >> 5, lane = t & 31;
    const int lq = lane >> 2, lr = lane & 3;
    const int wm = w & 3, wn = w >> 2;

    float4 pa[2], pw[2];

    auto ld = [&](int c) {
        int k0 = c * 16;
#pragma unroll
        for (int p = 0; p < 2; p++) {
            int i = t + 256 * p;
            int row = i >> 2, k4 = i & 3;
            pa[p] = *(const float4*)(Ap + (long)row * H + k0 + k4 * 4);
            int grow = ((row >> 3) & 3) * H + j0 + (row & 7) + ((row >> 5) << 3);
            pw[p] = *(const float4*)(Wp + (long)grow * H + k0 + k4 * 4);
        }
    };
    auto st = [&](int bf) {
#pragma unroll
        for (int p = 0; p < 2; p++) {
            int i = t + 256 * p;
            int row = i >> 2, k4 = i & 3;
            uint4 ua = make_uint4(f2tf(pa[p].x), f2tf(pa[p].y), f2tf(pa[p].z), f2tf(pa[p].w));
            uint4 uw = make_uint4(f2tf(pw[p].x), f2tf(pw[p].y), f2tf(pw[p].z), f2tf(pw[p].w));
            *(uint4*)&As[bf][row * 20 + k4 * 4] = ua;
            *(uint4*)&Ws[bf][row * 20 + k4 * 4] = uw;
        }
    };

    float acc[2][8][4];
#pragma unroll
    for (int mt = 0; mt < 2; mt++)
#pragma unroll
        for (int nt = 0; nt < 8; nt++)
#pragma unroll
            for (int v = 0; v < 4; v++) acc[mt][nt][v] = 0.f;

    ld(0); st(0);
    __syncthreads();

#pragma unroll 1
    for (int c = 0; c < 16; c++) {
        int cur = c & 1;
        if (c < 15) ld(c + 1);
#pragma unroll
        for (int k8s = 0; k8s < 2; k8s++) {
            int kb = k8s * 8;
            unsigned a[2][4];
#pragma unroll
            for (int mt = 0; mt < 2; mt++) {
                int r = wm * 32 + mt * 16 + lq;
                a[mt][0] = As[cur][r * 20 + kb + lr];
                a[mt][1] = As[cur][(r + 8) * 20 + kb + lr];
                a[mt][2] = As[cur][r * 20 + kb + lr + 4];
                a[mt][3] = As[cur][(r + 8) * 20 + kb + lr + 4];
            }
#pragma unroll
            for (int nt = 0; nt < 8; nt++) {
                int rn = wn * 64 + nt * 8 + lq;
                unsigned bb0 = Ws[cur][rn * 20 + kb + lr];
                unsigned bb1 = Ws[cur][rn * 20 + kb + lr + 4];
#pragma unroll
                for (int mt = 0; mt < 2; mt++)
                    mma_tf32(acc[mt][nt], a[mt][0], a[mt][1], a[mt][2], a[mt][3], bb0, bb1);
            }
        }
        if (c < 15) st(cur ^ 1);
        __syncthreads();
    }

    // ---- epilogue: per-(b,j) gates -> LSTM; acc nt = d*4+q, d = j-group ----
#pragma unroll
    for (int mt = 0; mt < 2; mt++) {
#pragma unroll
        for (int rh = 0; rh < 2; rh++) {
            int b_row = m0 + wm * 32 + mt * 16 + lq + rh * 8;
            float rv = DEC ? g_inp[itstep * B + b_row] : 0.f;
#pragma unroll
            for (int d = 0; d < 2; d++) {
                int j = j0 + (wn * 2 + d) * 8 + lr * 2;
                float gate[4][2];
#pragma unroll
                for (int q = 0; q < 4; q++) {
                    int nt = d * 4 + q;
                    float v0 = acc[mt][nt][rh * 2];
                    float v1 = acc[mt][nt][rh * 2 + 1];
                    int gg = q * H + j;
                    if (DEC) {
                        float2 x1 = *(const float2*)&b1[s * G + gg];
                        float2 x2 = *(const float2*)&b2[s * G + gg];
                        float2 xc = *(const float2*)&cvec[s * G + gg];
                        v0 += x1.x + x2.x + rv * xc.x;
                        v1 += x1.y + x2.y + rv * xc.y;
                    } else {
                        float2 xa = *(const float2*)&add[(long)s * sAddz + (long)b_row * G + gg];
                        v0 += xa.x; v1 += xa.y;
                    }
                    gate[q][0] = v0; gate[q][1] = v1;
                }
                long base = ((long)s * B + b_row) * H + j;
                float2 cold = *(const float2*)&g_c[base];
                float co[2] = {cold.x, cold.y};
                float hn[2], cn[2];
#pragma unroll
                for (int dd = 0; dd < 2; dd++) {
                    float c_ = sigf(gate[1][dd]) * co[dd] + sigf(gate[0][dd]) * tanhf(gate[2][dd]);
                    cn[dd] = c_;
                    hn[dd] = sigf(gate[3][dd]) * tanhf(c_);
                }
                *(float2*)&g_c[base] = make_float2(cn[0], cn[1]);
                *(float2*)&hout[base] = make_float2(hn[0], hn[1]);
            }
        }
    }

    // ---- fused attention for step lstep (reads hin = h(lstep)) ----
    if (DEC && lstep >= 0) {
        int bid = (blockIdx.z * 8 + blockIdx.y) * 8 + blockIdx.x;
        int gw = bid * 8 + w;                 // 4096 warps
#pragma unroll 1
        for (int rep = 0; rep < 2; rep++) {
            int sb = gw + rep * 4096;         // s*B + b
            int ss = sb >> 10;
            const float* hp = hin + (long)sb * H;
            float4 h0 = *(const float4*)&hp[lane * 4];
            float4 h1 = *(const float4*)&hp[128 + lane * 4];
            const float* wf = Wfcout + ss * 2 * H;
            float4 w0 = *(const float4*)&wf[lane * 4];
            float4 w1 = *(const float4*)&wf[128 + lane * 4];

            float red[T + 1];
            red[T] = h0.x * w0.x + h0.y * w0.y + h0.z * w0.z + h0.w * w0.w
                   + h1.x * w1.x + h1.y * w1.y + h1.z * w1.z + h1.w * w1.w;
#pragma unroll
            for (int tt = 0; tt < T; tt++) {
                const float* kp = g_k2 + ((long)tt * S * B + sb) * H;
                float4 k0 = *(const float4*)&kp[lane * 4];
                float4 k1 = *(const float4*)&kp[128 + lane * 4];
                red[tt] = h0.x * k0.x + h0.y * k0.y + h0.z * k0.z + h0.w * k0.w
                        + h1.x * k1.x + h1.y * k1.y + h1.z * k1.z + h1.w * k1.w;
            }
#pragma unroll
            for (int r = 0; r < T + 1; r++) {
                float v = red[r];
#pragma unroll
                for (int off = 16; off; off >>= 1) v += __shfl_xor_sync(0xffffffffu, v, off);
                red[r] = v;
            }
            float sc[T];
            float mx = -1e30f;
#pragma unroll
            for (int tt = 0; tt < T; tt++) {
                float v = (red[tt] + g_bqk[(long)tt * S * B + sb]) * 0.0625f;
                sc[tt] = v;
                mx = fmaxf(mx, v);
            }
            float sum = 0.f;
#pragma unroll
            for (int tt = 0; tt < T; tt++) { sc[tt] = __expf(sc[tt] - mx); sum += sc[tt]; }
            float inv = 1.f / sum;
            float ctxdot = 0.f;
#pragma unroll
            for (int tt = 0; tt < T; tt++)
                ctxdot = fmaf(sc[tt] * inv, g_vu[(long)tt * S * B + sb], ctxdot);
            if (lane == 0)
                g_outs[(long)lstep * S * B + sb] = red[T] + ctxdot + g_c1[ss];
        }
    }
}

// ---------------- per-(t,s,b) scalars ----------------
__global__ void pc_scal_kernel() {
    int gtid = blockIdx.x * blockDim.x + threadIdx.x;
    int warp = gtid >> 5;
    int lane = threadIdx.x & 31;
    if (warp >= T * S * B) return;
    int s = (warp >> 10) & 7;

    const float* ep = g_enc + (long)warp * H;
    const float* wb = g_wbqk + s * H;
    const float* wv = g_wvu + s * H;
    float db = 0.f, dv = 0.f;
#pragma unroll
    for (int u = 0; u < 2; u++) {
        int e = lane * 4 + u * 128;
        float4 ev = *(const float4*)&ep[e];
        float4 b4 = *(const float4*)&wb[e];
        float4 v4 = *(const float4*)&wv[e];
        db += ev.x * b4.x + ev.y * b4.y + ev.z * b4.z + ev.w * b4.w;
        dv += ev.x * v4.x + ev.y * v4.y + ev.z * v4.z + ev.w * v4.w;
    }
#pragma unroll
    for (int off = 16; off; off >>= 1) {
        db += __shfl_xor_sync(0xffffffffu, db, off);
        dv += __shfl_xor_sync(0xffffffffu, dv, off);
    }
    if (lane == 0) {
        g_bqk[warp] = db + g_cbqk[s];
        g_vu[warp]  = dv + g_cvu[s];
    }
}

// ---------------- standalone attention (last decoder step) ----------------
__global__ void dec_attn_kernel(const float* __restrict__ hcur,
                                const float* __restrict__ Wfcout, int l) {
    int gtid = blockIdx.x * blockDim.x + threadIdx.x;
    int warp = gtid >> 5;
    int lane = threadIdx.x & 31;
    if (warp >= S * B) return;
    int s = warp >> 10;

    const float* hp = hcur + (long)warp * H;
    float4 h0 = *(const float4*)&hp[lane * 4];
    float4 h1 = *(const float4*)&hp[128 + lane * 4];

    const float* wf = Wfcout + s * 2 * H;
    float4 w0 = *(const float4*)&wf[lane * 4];
    float4 w1 = *(const float4*)&wf[128 + lane * 4];

    float red[T + 1];
    red[T] = h0.x * w0.x + h0.y * w0.y + h0.z * w0.z + h0.w * w0.w
           + h1.x * w1.x + h1.y * w1.y + h1.z * w1.z + h1.w * w1.w;

#pragma unroll
    for (int tt = 0; tt < T; tt++) {
        const float* kp = g_k2 + ((long)tt * S * B + warp) * H;
        float4 k0 = *(const float4*)&kp[lane * 4];
        float4 k1 = *(const float4*)&kp[128 + lane * 4];
        red[tt] = h0.x * k0.x + h0.y * k0.y + h0.z * k0.z + h0.w * k0.w
                + h1.x * k1.x + h1.y * k1.y + h1.z * k1.z + h1.w * k1.w;
    }
#pragma unroll
    for (int r = 0; r < T + 1; r++) {
        float v = red[r];
#pragma unroll
        for (int off = 16; off; off >>= 1) v += __shfl_xor_sync(0xffffffffu, v, off);
        red[r] = v;
    }

    float sc[T];
    float mx = -1e30f;
#pragma unroll
    for (int tt = 0; tt < T; tt++) {
        float v = (red[tt] + g_bqk[(long)tt * S * B + warp]) * 0.0625f;
        sc[tt] = v;
        mx = fmaxf(mx, v);
    }
    float sum = 0.f;
#pragma unroll
    for (int tt = 0; tt < T; tt++) { sc[tt] = __expf(sc[tt] - mx); sum += sc[tt]; }
    float inv = 1.f / sum;
    float ctxdot = 0.f;
#pragma unroll
    for (int tt = 0; tt < T; tt++)
        ctxdot = fmaf(sc[tt] * inv, g_vu[(long)tt * S * B + warp], ctxdot);

    if (lane == 0)
        g_outs[(long)l * S * B + warp] = red[T] + ctxdot + g_c1[s];
}

// ---------------- final 8->1 mix ----------------
__global__ void final_kernel(const float* __restrict__ Wfc, const float* __restrict__ bfc,
                             float* __restrict__ out) {
    int i = blockIdx.x * blockDim.x + threadIdx.x;
    if (i >= B * L) return;
    int b = i / L, l = i % L;
    float acc = bfc[0];
#pragma unroll
    for (int s = 0; s < S; s++)
        acc += g_outs[(long)l * S * B + (long)s * B + b] * Wfc[s];
    out[i] = acc;
}

// ---------------- host launch ----------------
extern "C" void kernel_launch(void* const* d_in, const int* in_sizes, int n_in,
                              void* d_out, int out_size) {
    const float* x       = (const float*)d_in[0];
    const float* tgt     = (const float*)d_in[1];
    const float* W_ih_e  = (const float*)d_in[2];
    const float* W_hh_e  = (const float*)d_in[3];
    const float* b_ih_e  = (const float*)d_in[4];
    const float* b_hh_e  = (const float*)d_in[5];
    const float* W_ih_d  = (const float*)d_in[6];
    const float* W_hh_d  = (const float*)d_in[7];
    const float* b_ih_d  = (const float*)d_in[8];
    const float* b_hh_d  = (const float*)d_in[9];
    const float* W_in    = (const float*)d_in[10];
    const float* b_in    = (const float*)d_in[11];
    const float* W_out   = (const float*)d_in[12];
    const float* b_out   = (const float*)d_in[13];
    const float* W_fcout = (const float*)d_in[14];
    const float* b_fcout = (const float*)d_in[15];
    const float* W_fc    = (const float*)d_in[16];
    const float* b_fc    = (const float*)d_in[17];
    float* out = (float*)d_out;

    float *Gin, *enc, *k2, *hA, *hB, *M1, *k2b;
    cudaGetSymbolAddress((void**)&Gin, g_Gin);
    cudaGetSymbolAddress((void**)&enc, g_enc);
    cudaGetSymbolAddress((void**)&k2,  g_k2);
    cudaGetSymbolAddress((void**)&hA,  g_hA);
    cudaGetSymbolAddress((void**)&hB,  g_hB);
    cudaGetSymbolAddress((void**)&M1,  g_M1);
    cudaGetSymbolAddress((void**)&k2b, g_k2b);

    prep_kernel<<<(S * B * H + 255) / 256, 256>>>(x, tgt);
    pc_a<<<(S * H + 255) / 256, 256>>>(W_out, W_fcout, W_in, b_in);
    pc_b<<<(S * H + 255) / 256, 256>>>(W_in, b_in, W_fcout, b_fcout, b_out);
    pc_m1<<<dim3(16, 16, 8), dim3(16, 16)>>>(W_in);

    // 1) encoder input projections (biases folded): Gin[z=s*12+t][b][g]
    gemm_tc<<<dim3(G / 128, B / 128, 96), 256>>>(
        x, (long)F, 96 * F,
        W_ih_e, (long)G * F, F,
        b_ih_e, b_hh_e, G,
        Gin, (long)B * G, G, F, 12);

    // 2) encoder recurrence: h(t) -> g_enc[t]
    const dim3 sgrid(H / 32, B / 128, S);
    for (int tt = 0; tt < T; tt++) {
        const float* hin = (tt == 0) ? hA : (enc + (long)(tt - 1) * S * B * H);
        step_k<0><<<sgrid, 256>>>(
            hin, enc + (long)tt * S * B * H, W_hh_e,
            nullptr, nullptr, nullptr,
            Gin + (long)tt * B * G, 12l * B * G,
            nullptr, 0, -1);
    }

    // 3) per-key scalars + transformed keys
    pc_scal_kernel<<<(T * S * B * 32 + 255) / 256, 256>>>();
    gemm_tc<<<dim3(H / 128, B / 128, T * S), 256>>>(
        enc, (long)B * H, H,
        M1, (long)H * H, H,
        k2b, nullptr, H,
        k2, (long)B * H, H, H, 1);

    // 4) decoder: gates(l) + fused attention(l-1), 48 launches
    for (int l = 0; l < L; l++) {
        const float* hin = (l == 0) ? (enc + (long)11 * S * B * H)
                                    : ((l & 1) ? hA : hB);   // h(l-1)
        float* hout = (l & 1) ? hB : hA;                     // h(l)
        step_k<1><<<sgrid, 256>>>(
            hin, hout, W_hh_d,
            b_ih_d, b_hh_d, W_ih_d,
            nullptr, 0,
            W_fcout, l, l - 1);
    }
    // attention for the last step
    dec_attn_kernel<<<(S * B * 32 + 255) / 256, 256>>>(
        (L & 1) ? hA : hB, W_fcout, L - 1);

    // 5) final mix
    final_kernel<<<(B * L + 255) / 256, 256>>>(W_fc, b_fc, out);
}

// round 7
// speedup vs baseline: 1.5399x; 1.3402x over previous
#include <cuda_runtime.h>
#include <cuda_fp16.h>
#include <math.h>

// ---------------- problem constants ----------------
#define S   8
#define T   12
#define H   256
#define F   316
#define B   1024
#define L   48
#define G   1024      // 4*H
#define PH  40        // smem row pitch in halves (conflict-free for 20-word rows)

// ---------------- scratch (device globals; no allocs allowed) ----------------
__device__ float  g_Gin[96l * B * G];           // encoder input gates [s*12+t][b][g]
__device__ float  g_enc[(long)T * S * B * H];   // encoder outputs f32 [t][s][b][h]
__device__ float  g_k2 [(long)T * S * B * H];   // transformed keys [t][s][b][h]
__device__ __half g_h16A[S * B * H];            // fp16 h ping-pong
__device__ __half g_h16B[S * B * H];
__device__ __half g_W16e[(long)S * G * H];      // enc W_hh fp16, gate-interleaved
__device__ __half g_W16d[(long)S * G * H];      // dec W_hh fp16, gate-interleaved
__device__ float  g_c  [S * B * H];
__device__ float  g_inp[L * B];
__device__ float  g_outs[(long)L * S * B];
// small precomputed tensors
__device__ float g_M1   [S * H * H];   // Wq^T @ Wk per stream
__device__ float g_u    [S * H];
__device__ float g_wbqk [S * H];
__device__ float g_wvu  [S * H];
__device__ float g_k2b  [S * H];
__device__ float g_cbqk [S];
__device__ float g_cvu  [S];
__device__ float g_c1   [S];
__device__ float g_bqk  [(long)T * S * B];
__device__ float g_vu   [(long)T * S * B];

__device__ __forceinline__ float sigf(float x) { return 1.f / (1.f + __expf(-x)); }

__device__ __forceinline__ unsigned f2tf(float f) {
    unsigned u;
    asm("cvt.rna.tf32.f32 %0, %1;" : "=r"(u) : "f"(f));
    return u;
}

__device__ __forceinline__ void mma_tf32(float c[4],
    unsigned a0, unsigned a1, unsigned a2, unsigned a3,
    unsigned b0, unsigned b1)
{
    asm volatile(
        "mma.sync.aligned.m16n8k8.row.col.f32.tf32.tf32.f32 "
        "{%0,%1,%2,%3}, {%4,%5,%6,%7}, {%8,%9}, {%0,%1,%2,%3};"
        : "+f"(c[0]), "+f"(c[1]), "+f"(c[2]), "+f"(c[3])
        : "r"(a0), "r"(a1), "r"(a2), "r"(a3), "r"(b0), "r"(b1));
}

__device__ __forceinline__ void mma_f16(float c[4],
    unsigned a0, unsigned a1, unsigned a2, unsigned a3,
    unsigned b0, unsigned b1)
{
    asm volatile(
        "mma.sync.aligned.m16n8k16.row.col.f32.f16.f16.f32 "
        "{%0,%1,%2,%3}, {%4,%5,%6,%7}, {%8,%9}, {%0,%1,%2,%3};"
        : "+f"(c[0]), "+f"(c[1]), "+f"(c[2]), "+f"(c[3])
        : "r"(a0), "r"(a1), "r"(a2), "r"(a3), "r"(b0), "r"(b1));
}

__device__ __forceinline__ unsigned sptr(const void* p) {
    return (unsigned)__cvta_generic_to_shared(p);
}
__device__ __forceinline__ void cp16(void* s, const void* g) {
    asm volatile("cp.async.cg.shared.global [%0], [%1], 16;" :: "r"(sptr(s)), "l"(g));
}

// ---------------- prep ----------------
__global__ void prep_kernel(const float* __restrict__ x, const float* __restrict__ tgt) {
    int i = blockIdx.x * blockDim.x + threadIdx.x;
    if (i < S * B * H) { g_h16A[i] = __float2half(0.f); g_c[i] = 0.f; }
    if (i < L * B) {
        int l = i / B, b = i % B;
        g_inp[i] = (l == 0) ? x[(long)b * 96 * F + 95 * F + 0]
                            : tgt[(long)b * L + (l - 1)];
    }
}

// ---------------- weight conversion: f32 [s][4H][H] -> fp16 gate-interleaved ----
// dst layout [s][jblk 0..7][r 0..127][k 0..255]; r -> gate q=(r>>3)&3,
// jloc=(r&7)+((r>>5)<<3); src row = q*H + jblk*32 + jloc.
__global__ void conv_w16(const float* __restrict__ W, __half* __restrict__ dst) {
    long i = (long)blockIdx.x * 256 + threadIdx.x;   // over S*8*128*256
    int k = i & 255;
    long rr = i >> 8;
    int r = rr & 127;
    long jj_ = rr >> 7;
    int jb = jj_ & 7;
    int s = (int)(jj_ >> 3);
    int q = (r >> 3) & 3;
    int jloc = (r & 7) + ((r >> 5) << 3);
    dst[i] = __float2half(W[(long)s * G * H + (q * H + jb * 32 + jloc) * (long)H + k]);
}

// ---------------- small precomputes (one-time) ----------------
__global__ void pc_a(const float* __restrict__ Wout, const float* __restrict__ Wfcout,
                     const float* __restrict__ Win,  const float* __restrict__ b_in) {
    int t = blockIdx.x * blockDim.x + threadIdx.x;
    if (t >= S * H) return;
    int s = t >> 8, e = t & 255;
    const float* wf2 = Wfcout + s * 2 * H + H;
    const float* Wo  = Wout + (long)s * H * H;
    float u = 0.f;
    for (int o = 0; o < H; o++) u += wf2[o] * Wo[o * H + e];
    g_u[t] = u;
    const float* bq = b_in + s * 3 * H;
    const float* bk = bq + H;
    const float* Wq = Win + (long)s * 3 * H * H;
    const float* Wk = Wq + H * H;
    float wb = 0.f, kb = 0.f;
    for (int e2 = 0; e2 < H; e2++) {
        wb += bq[e2] * Wk[e2 * H + e];
        kb += Wq[e2 * H + e] * bk[e2];
    }
    g_wbqk[t] = wb;
    g_k2b[t]  = kb;
}

__global__ void pc_b(const float* __restrict__ Win, const float* __restrict__ b_in,
                     const float* __restrict__ Wfcout, const float* __restrict__ b_fcout,
                     const float* __restrict__ b_out) {
    int t = blockIdx.x * blockDim.x + threadIdx.x;
    if (t >= S * H) return;
    int s = t >> 8, h = t & 255;
    const float* Wv = Win + (long)s * 3 * H * H + 2 * H * H;
    float wv = 0.f;
    for (int e = 0; e < H; e++) wv += g_u[s * H + e] * Wv[e * H + h];
    g_wvu[t] = wv;
    if (h == 0) {
        const float* bq = b_in + s * 3 * H;
        const float* bk = bq + H;
        const float* bv = bq + 2 * H;
        const float* wf2 = Wfcout + s * 2 * H + H;
        const float* bo  = b_out + s * H;
        float cvu = 0.f, cb = 0.f, c1 = 0.f;
        for (int e = 0; e < H; e++) {
            cvu += g_u[s * H + e] * bv[e];
            cb  += bq[e] * bk[e];
            c1  += wf2[e] * bo[e];
        }
        g_cvu[s]  = cvu;
        g_cbqk[s] = cb;
        g_c1[s]   = c1 + b_fcout[s];
    }
}

__global__ void pc_m1(const float* __restrict__ Win) {
    __shared__ float tq[16][17];
    __shared__ float tk[16][17];
    int s = blockIdx.z;
    const float* Wq = Win + (long)s * 3 * H * H;
    const float* Wk = Wq + H * H;
    int tyy = threadIdx.y, txx = threadIdx.x;
    int hq = blockIdx.y * 16 + tyy;
    int hk = blockIdx.x * 16 + txx;
    float acc = 0.f;
    for (int e0 = 0; e0 < H; e0 += 16) {
        tq[tyy][txx] = Wq[(e0 + tyy) * H + blockIdx.y * 16 + txx];
        tk[tyy][txx] = Wk[(e0 + tyy) * H + hk];
        __syncthreads();
#pragma unroll
        for (int ee = 0; ee < 16; ee++)
            acc = fmaf(tq[ee][tyy], tk[ee][txx], acc);
        __syncthreads();
    }
    g_M1[(long)s * H * H + hq * H + hk] = acc;
}

// ================= generic tf32 tensor-core GEMM (Gin, k2) =================
__global__ void __launch_bounds__(256) gemm_tc(
    const float* __restrict__ Ag, long sAz, int lda,
    const float* __restrict__ Wg, long sWz, int ldw,
    const float* __restrict__ b1, const float* __restrict__ b2, long sBz,
    float* __restrict__ C, long sCz, int ldc,
    int K, int wdiv)
{
    __shared__ unsigned As[2][128 * 20];
    __shared__ unsigned Ws[2][128 * 20];

    const int z  = blockIdx.z;
    const int wi = (z / wdiv) & 7;
    const int m0 = blockIdx.y * 128;
    const int n0 = blockIdx.x * 128;

    const float* Ap = Ag + (long)z * sAz + (long)m0 * lda;
    const float* Wp = Wg + (long)wi * sWz + (long)n0 * ldw;

    const int t = threadIdx.x;
    const int w = t >> 5, lane = t & 31;
    const int lq = lane >> 2, lr = lane & 3;
    const int wm = w & 3, wn = w >> 2;

    float4 pa[2], pw[2];

    auto ld = [&](int c) {
        int k0 = c * 16;
#pragma unroll
        for (int p = 0; p < 2; p++) {
            int i = t + 256 * p;
            int row = i >> 2, k4 = i & 3;
            int k = k0 + k4 * 4;
            if (k < K) {
                pa[p] = *(const float4*)(Ap + (long)row * lda + k);
                pw[p] = *(const float4*)(Wp + (long)row * ldw + k);
            } else {
                pa[p] = make_float4(0.f, 0.f, 0.f, 0.f);
                pw[p] = make_float4(0.f, 0.f, 0.f, 0.f);
            }
        }
    };
    auto st = [&](int bf) {
#pragma unroll
        for (int p = 0; p < 2; p++) {
            int i = t + 256 * p;
            int row = i >> 2, k4 = i & 3;
            uint4 ua = make_uint4(f2tf(pa[p].x), f2tf(pa[p].y), f2tf(pa[p].z), f2tf(pa[p].w));
            uint4 uw = make_uint4(f2tf(pw[p].x), f2tf(pw[p].y), f2tf(pw[p].z), f2tf(pw[p].w));
            *(uint4*)&As[bf][row * 20 + k4 * 4] = ua;
            *(uint4*)&Ws[bf][row * 20 + k4 * 4] = uw;
        }
    };

    float acc[2][8][4];
#pragma unroll
    for (int mt = 0; mt < 2; mt++)
#pragma unroll
        for (int nt = 0; nt < 8; nt++)
#pragma unroll
            for (int v = 0; v < 4; v++) acc[mt][nt][v] = 0.f;

    const int NC = (K + 15) / 16;
    ld(0); st(0);
    __syncthreads();

    for (int c = 0; c < NC; c++) {
        int cur = c & 1;
        if (c + 1 < NC) ld(c + 1);
#pragma unroll
        for (int k8s = 0; k8s < 2; k8s++) {
            int kb = k8s * 8;
            unsigned a[2][4];
#pragma unroll
            for (int mt = 0; mt < 2; mt++) {
                int r = wm * 32 + mt * 16 + lq;
                a[mt][0] = As[cur][r * 20 + kb + lr];
                a[mt][1] = As[cur][(r + 8) * 20 + kb + lr];
                a[mt][2] = As[cur][r * 20 + kb + lr + 4];
                a[mt][3] = As[cur][(r + 8) * 20 + kb + lr + 4];
            }
#pragma unroll
            for (int nt = 0; nt < 8; nt++) {
                int rn = wn * 64 + nt * 8 + lq;
                unsigned bb0 = Ws[cur][rn * 20 + kb + lr];
                unsigned bb1 = Ws[cur][rn * 20 + kb + lr + 4];
#pragma unroll
                for (int mt = 0; mt < 2; mt++)
                    mma_tf32(acc[mt][nt], a[mt][0], a[mt][1], a[mt][2], a[mt][3], bb0, bb1);
            }
        }
        if (c + 1 < NC) st(cur ^ 1);
        __syncthreads();
    }

    C += (long)z * sCz;
#pragma unroll
    for (int mt = 0; mt < 2; mt++) {
#pragma unroll
        for (int nt = 0; nt < 8; nt++) {
#pragma unroll
            for (int rh = 0; rh < 2; rh++) {
                int m = m0 + wm * 32 + mt * 16 + lq + rh * 8;
                int n = n0 + wn * 64 + nt * 8 + lr * 2;
                float v0 = acc[mt][nt][rh * 2];
                float v1 = acc[mt][nt][rh * 2 + 1];
                if (b1) { v0 += b1[(long)wi * sBz + n]; v1 += b1[(long)wi * sBz + n + 1]; }
                if (b2) { v0 += b2[(long)wi * sBz + n]; v1 += b2[(long)wi * sBz + n + 1]; }
                *(float2*)&C[(long)m * ldc + n] = make_float2(v0, v1);
            }
        }
    }
}

// ---------------- shared attention device function (fp16 h) ----------------
__device__ __forceinline__ void attn_one(const __half* __restrict__ hbase, int sb, int lane,
                                         const float* __restrict__ Wfcout, int lstep)
{
    int ss = sb >> 10;
    const __half2* hp2 = (const __half2*)(hbase + (long)sb * H);
    float2 hf[4];
    {
        __half2 v0 = hp2[lane * 2], v1 = hp2[lane * 2 + 1];
        __half2 v2 = hp2[64 + lane * 2], v3 = hp2[65 + lane * 2];
        hf[0] = __half22float2(v0); hf[1] = __half22float2(v1);
        hf[2] = __half22float2(v2); hf[3] = __half22float2(v3);
    }
    const float* wf = Wfcout + ss * 2 * H;
    float4 w0 = *(const float4*)&wf[lane * 4];
    float4 w1 = *(const float4*)&wf[128 + lane * 4];

    float red[T + 1];
    red[T] = hf[0].x * w0.x + hf[0].y * w0.y + hf[1].x * w0.z + hf[1].y * w0.w
           + hf[2].x * w1.x + hf[2].y * w1.y + hf[3].x * w1.z + hf[3].y * w1.w;
#pragma unroll
    for (int tt = 0; tt < T; tt++) {
        const float* kp = g_k2 + ((long)tt * S * B + sb) * H;
        float4 k0 = *(const float4*)&kp[lane * 4];
        float4 k1 = *(const float4*)&kp[128 + lane * 4];
        red[tt] = hf[0].x * k0.x + hf[0].y * k0.y + hf[1].x * k0.z + hf[1].y * k0.w
                + hf[2].x * k1.x + hf[2].y * k1.y + hf[3].x * k1.z + hf[3].y * k1.w;
    }
#pragma unroll
    for (int r = 0; r < T + 1; r++) {
        float v = red[r];
#pragma unroll
        for (int off = 16; off; off >>= 1) v += __shfl_xor_sync(0xffffffffu, v, off);
        red[r] = v;
    }
    float sc[T];
    float mx = -1e30f;
#pragma unroll
    for (int tt = 0; tt < T; tt++) {
        float v = (red[tt] + g_bqk[(long)tt * S * B + sb]) * 0.0625f;
        sc[tt] = v;
        mx = fmaxf(mx, v);
    }
    float sum = 0.f;
#pragma unroll
    for (int tt = 0; tt < T; tt++) { sc[tt] = __expf(sc[tt] - mx); sum += sc[tt]; }
    float inv = 1.f / sum;
    float ctxdot = 0.f;
#pragma unroll
    for (int tt = 0; tt < T; tt++)
        ctxdot = fmaf(sc[tt] * inv, g_vu[(long)tt * S * B + sb], ctxdot);
    if (lane == 0)
        g_outs[(long)lstep * S * B + sb] = red[T] + ctxdot + g_c1[ss];
}

// ================= fp16 fused step kernel: gates GEMM + LSTM (+ prev attn) ====
// 256 thr / 8 warps, tile 128 b-rows x 128 n (4 gates x 32 j), K=256, BK=32.
// W16 pre-interleaved [s][jblk][128][256]; A = h16. cp.async double-buffered.
// m16n8k16 f16 MMA, f32 accum. Epilogue: extras + LSTM, h -> half2.
template <int DEC>
__global__ void __launch_bounds__(256, 2) step16_k(
    const __half* __restrict__ hin, __half* __restrict__ hout,
    const __half* __restrict__ W16,
    const float* __restrict__ b1, const float* __restrict__ b2,
    const float* __restrict__ cvec,
    const float* __restrict__ add, long sAddz,
    float* __restrict__ encout,
    const float* __restrict__ Wfcout,
    int itstep, int lstep)
{
    __shared__ __align__(16) __half As[2][128 * PH];
    __shared__ __align__(16) __half Ws[2][128 * PH];

    const int s  = blockIdx.z;
    const int m0 = blockIdx.y * 128;
    const int j0 = blockIdx.x * 32;

    const __half* Aph = hin + ((long)s * B + m0) * H;
    const __half* Wph = W16 + ((long)(s * 8 + blockIdx.x) * 128) * H;

    const int t = threadIdx.x;
    const int w = t >> 5, lane = t & 31;
    const int lq = lane >> 2, lr = lane & 3;
    const int wm = w & 3, wn = w >> 2;

    auto issue = [&](int cidx) {
        int buf = cidx & 1;
        int k0 = cidx * 32;
#pragma unroll
        for (int p = 0; p < 2; p++) {
            int idx = t + 256 * p;
            int row = idx >> 2, seg = idx & 3;
            cp16(&As[buf][row * PH + seg * 8], Aph + (long)row * H + k0 + seg * 8);
            cp16(&Ws[buf][row * PH + seg * 8], Wph + (long)row * H + k0 + seg * 8);
        }
        asm volatile("cp.async.commit_group;");
    };

    float acc[2][8][4];
#pragma unroll
    for (int mt = 0; mt < 2; mt++)
#pragma unroll
        for (int nt = 0; nt < 8; nt++)
#pragma unroll
            for (int v = 0; v < 4; v++) acc[mt][nt][v] = 0.f;

    issue(0);

#pragma unroll 1
    for (int c = 0; c < 8; c++) {
        if (c < 7) {
            issue(c + 1);
            asm volatile("cp.async.wait_group 1;");
        } else {
            asm volatile("cp.async.wait_group 0;");
        }
        __syncthreads();
        int buf = c & 1;
#pragma unroll
        for (int k16 = 0; k16 < 2; k16++) {
            int kb = k16 * 16;
            unsigned a[2][4];
#pragma unroll
            for (int mt = 0; mt < 2; mt++) {
                int r = wm * 32 + mt * 16 + lq;
                a[mt][0] = *(const unsigned*)&As[buf][r * PH + kb + lr * 2];
                a[mt][1] = *(const unsigned*)&As[buf][(r + 8) * PH + kb + lr * 2];
                a[mt][2] = *(const unsigned*)&As[buf][r * PH + kb + 8 + lr * 2];
                a[mt][3] = *(const unsigned*)&As[buf][(r + 8) * PH + kb + 8 + lr * 2];
            }
#pragma unroll
            for (int nt = 0; nt < 8; nt++) {
                int rn = wn * 64 + nt * 8 + lq;
                unsigned bb0 = *(const unsigned*)&Ws[buf][rn * PH + kb + lr * 2];
                unsigned bb1 = *(const unsigned*)&Ws[buf][rn * PH + kb + 8 + lr * 2];
#pragma unroll
                for (int mt = 0; mt < 2; mt++)
                    mma_f16(acc[mt][nt], a[mt][0], a[mt][1], a[mt][2], a[mt][3], bb0, bb1);
            }
        }
        __syncthreads();
    }

    // ---- epilogue: per-(b,j) gates -> LSTM; acc nt = d*4+q ----
#pragma unroll
    for (int mt = 0; mt < 2; mt++) {
#pragma unroll
        for (int rh = 0; rh < 2; rh++) {
            int b_row = m0 + wm * 32 + mt * 16 + lq + rh * 8;
            float rv = DEC ? g_inp[itstep * B + b_row] : 0.f;
#pragma unroll
            for (int d = 0; d < 2; d++) {
                int j = j0 + (wn * 2 + d) * 8 + lr * 2;
                float gate[4][2];
#pragma unroll
                for (int q = 0; q < 4; q++) {
                    int nt = d * 4 + q;
                    float v0 = acc[mt][nt][rh * 2];
                    float v1 = acc[mt][nt][rh * 2 + 1];
                    int gg = q * H + j;
                    if (DEC) {
                        float2 x1 = *(const float2*)&b1[s * G + gg];
                        float2 x2 = *(const float2*)&b2[s * G + gg];
                        float2 xc = *(const float2*)&cvec[s * G + gg];
                        v0 += x1.x + x2.x + rv * xc.x;
                        v1 += x1.y + x2.y + rv * xc.y;
                    } else {
                        float2 xa = *(const float2*)&add[(long)s * sAddz + (long)b_row * G + gg];
                        v0 += xa.x; v1 += xa.y;
                    }
                    gate[q][0] = v0; gate[q][1] = v1;
                }
                long base = ((long)s * B + b_row) * H + j;
                float2 cold = *(const float2*)&g_c[base];
                float co[2] = {cold.x, cold.y};
                float hn[2], cn[2];
#pragma unroll
                for (int dd = 0; dd < 2; dd++) {
                    float c_ = sigf(gate[1][dd]) * co[dd] + sigf(gate[0][dd]) * tanhf(gate[2][dd]);
                    cn[dd] = c_;
                    hn[dd] = sigf(gate[3][dd]) * tanhf(c_);
                }
                *(float2*)&g_c[base] = make_float2(cn[0], cn[1]);
                *(__half2*)&hout[base] = __floats2half2_rn(hn[0], hn[1]);
                if (!DEC) *(float2*)&encout[base] = make_float2(hn[0], hn[1]);
            }
        }
    }

    // ---- fused attention for step lstep (reads hin = h16(lstep)) ----
    if (DEC && lstep >= 0) {
        int bid = (blockIdx.z * 8 + blockIdx.y) * 8 + blockIdx.x;
        int gw = bid * 8 + w;                 // 4096 warps
#pragma unroll 1
        for (int rep = 0; rep < 2; rep++)
            attn_one(hin, gw + rep * 4096, lane, Wfcout, lstep);
    }
}

// ---------------- per-(t,s,b) scalars ----------------
__global__ void pc_scal_kernel() {
    int gtid = blockIdx.x * blockDim.x + threadIdx.x;
    int warp = gtid >> 5;
    int lane = threadIdx.x & 31;
    if (warp >= T * S * B) return;
    int s = (warp >> 10) & 7;

    const float* ep = g_enc + (long)warp * H;
    const float* wb = g_wbqk + s * H;
    const float* wv = g_wvu + s * H;
    float db = 0.f, dv = 0.f;
#pragma unroll
    for (int u = 0; u < 2; u++) {
        int e = lane * 4 + u * 128;
        float4 ev = *(const float4*)&ep[e];
        float4 b4 = *(const float4*)&wb[e];
        float4 v4 = *(const float4*)&wv[e];
        db += ev.x * b4.x + ev.y * b4.y + ev.z * b4.z + ev.w * b4.w;
        dv += ev.x * v4.x + ev.y * v4.y + ev.z * v4.z + ev.w * v4.w;
    }
#pragma unroll
    for (int off = 16; off; off >>= 1) {
        db += __shfl_xor_sync(0xffffffffu, db, off);
        dv += __shfl_xor_sync(0xffffffffu, dv, off);
    }
    if (lane == 0) {
        g_bqk[warp] = db + g_cbqk[s];
        g_vu[warp]  = dv + g_cvu[s];
    }
}

// ---------------- standalone attention (last decoder step) ----------------
__global__ void dec_attn_kernel(const __half* __restrict__ hcur,
                                const float* __restrict__ Wfcout, int l) {
    int gtid = blockIdx.x * blockDim.x + threadIdx.x;
    int warp = gtid >> 5;
    int lane = threadIdx.x & 31;
    if (warp >= S * B) return;
    attn_one(hcur, warp, lane, Wfcout, l);
}

// ---------------- final 8->1 mix ----------------
__global__ void final_kernel(const float* __restrict__ Wfc, const float* __restrict__ bfc,
                             float* __restrict__ out) {
    int i = blockIdx.x * blockDim.x + threadIdx.x;
    if (i >= B * L) return;
    int b = i / L, l = i % L;
    float acc = bfc[0];
#pragma unroll
    for (int s = 0; s < S; s++)
        acc += g_outs[(long)l * S * B + (long)s * B + b] * Wfc[s];
    out[i] = acc;
}

// ---------------- host launch ----------------
extern "C" void kernel_launch(void* const* d_in, const int* in_sizes, int n_in,
                              void* d_out, int out_size) {
    const float* x       = (const float*)d_in[0];
    const float* tgt     = (const float*)d_in[1];
    const float* W_ih_e  = (const float*)d_in[2];
    const float* W_hh_e  = (const float*)d_in[3];
    const float* b_ih_e  = (const float*)d_in[4];
    const float* b_hh_e  = (const float*)d_in[5];
    const float* W_ih_d  = (const float*)d_in[6];
    const float* W_hh_d  = (const float*)d_in[7];
    const float* b_ih_d  = (const float*)d_in[8];
    const float* b_hh_d  = (const float*)d_in[9];
    const float* W_in    = (const float*)d_in[10];
    const float* b_in    = (const float*)d_in[11];
    const float* W_out   = (const float*)d_in[12];
    const float* b_out   = (const float*)d_in[13];
    const float* W_fcout = (const float*)d_in[14];
    const float* b_fcout = (const float*)d_in[15];
    const float* W_fc    = (const float*)d_in[16];
    const float* b_fc    = (const float*)d_in[17];
    float* out = (float*)d_out;

    float *Gin, *enc, *k2, *M1, *k2b;
    __half *h16[2], *W16e, *W16d;
    cudaGetSymbolAddress((void**)&Gin, g_Gin);
    cudaGetSymbolAddress((void**)&enc, g_enc);
    cudaGetSymbolAddress((void**)&k2,  g_k2);
    cudaGetSymbolAddress((void**)&M1,  g_M1);
    cudaGetSymbolAddress((void**)&k2b, g_k2b);
    cudaGetSymbolAddress((void**)&h16[0], g_h16A);
    cudaGetSymbolAddress((void**)&h16[1], g_h16B);
    cudaGetSymbolAddress((void**)&W16e, g_W16e);
    cudaGetSymbolAddress((void**)&W16d, g_W16d);

    prep_kernel<<<(S * B * H + 255) / 256, 256>>>(x, tgt);
    conv_w16<<<(int)((long)S * G * H / 256), 256>>>(W_hh_e, W16e);
    conv_w16<<<(int)((long)S * G * H / 256), 256>>>(W_hh_d, W16d);
    pc_a<<<(S * H + 255) / 256, 256>>>(W_out, W_fcout, W_in, b_in);
    pc_b<<<(S * H + 255) / 256, 256>>>(W_in, b_in, W_fcout, b_fcout, b_out);
    pc_m1<<<dim3(16, 16, 8), dim3(16, 16)>>>(W_in);

    // 1) encoder input projections (biases folded): Gin[z=s*12+t][b][g]
    gemm_tc<<<dim3(G / 128, B / 128, 96), 256>>>(
        x, (long)F, 96 * F,
        W_ih_e, (long)G * F, F,
        b_ih_e, b_hh_e, G,
        Gin, (long)B * G, G, F, 12);

    // 2) encoder recurrence: h16 ping-pong, f32 copy -> g_enc[t]
    const dim3 sgrid(8, 8, 8);
    for (int tt = 0; tt < T; tt++) {
        step16_k<0><<<sgrid, 256>>>(
            h16[tt & 1], h16[(tt + 1) & 1], W16e,
            nullptr, nullptr, nullptr,
            Gin + (long)tt * B * G, 12l * B * G,
            enc + (long)tt * S * B * H,
            nullptr, 0, -1);
    }

    // 3) per-key scalars + transformed keys
    pc_scal_kernel<<<(T * S * B * 32 + 255) / 256, 256>>>();
    gemm_tc<<<dim3(H / 128, B / 128, T * S), 256>>>(
        enc, (long)B * H, H,
        M1, (long)H * H, H,
        k2b, nullptr, H,
        k2, (long)B * H, H, H, 1);

    // 4) decoder: gates(l) + fused attention(l-1); h16 ping-pong continues
    for (int l = 0; l < L; l++) {
        step16_k<1><<<sgrid, 256>>>(
            h16[l & 1], h16[(l + 1) & 1], W16d,
            b_ih_d, b_hh_d, W_ih_d,
            nullptr, 0,
            nullptr,
            W_fcout, l, l - 1);
    }
    // attention for the last step: h(47) lives in h16[L & 1 ^ ... ] = h16[(L)&1]
    dec_attn_kernel<<<(S * B * 32 + 255) / 256, 256>>>(h16[L & 1], W_fcout, L - 1);

    // 5) final mix
    final_kernel<<<(B * L + 255) / 256, 256>>>(W_fc, b_fc, out);
}

// round 8
// speedup vs baseline: 1.8627x; 1.2096x over previous
#include <cuda_runtime.h>
#include <cuda_fp16.h>
#include <math.h>

// ---------------- problem constants ----------------
#define S   8
#define T   12
#define H   256
#define F   316
#define B   1024
#define L   48
#define G   1024      // 4*H
#define PH  40        // Ws smem pitch (halves)
#define PA  264       // A-full smem pitch (halves); 264/2=132 ==4 mod 32 -> conflict-free
#define STEP_SMEM (128 * PA * 2 + 2 * 128 * PH * 2)   // 67584 + 20480 = 88064 B

// ---------------- scratch (device globals; no allocs allowed) ----------------
__device__ float  g_Gin[96l * B * G];           // encoder input gates [s*12+t][b][g]
__device__ float  g_enc[(long)T * S * B * H];   // encoder outputs f32 [t][s][b][h]
__device__ __half g_k2h[(long)T * S * B * H];   // transformed keys fp16
__device__ __half g_h16A[S * B * H];            // fp16 h ping-pong
__device__ __half g_h16B[S * B * H];
__device__ __half g_W16e[(long)S * G * H];      // enc W_hh fp16, gate-interleaved
__device__ __half g_W16d[(long)S * G * H];      // dec W_hh fp16, gate-interleaved
__device__ float  g_c  [S * B * H];
__device__ float  g_inp[L * B];
__device__ float  g_outs[(long)L * S * B];
// small precomputed tensors
__device__ float g_M1   [S * H * H];   // Wq^T @ Wk per stream
__device__ float g_u    [S * H];
__device__ float g_wbqk [S * H];
__device__ float g_wvu  [S * H];
__device__ float g_k2b  [S * H];
__device__ float g_cbqk [S];
__device__ float g_cvu  [S];
__device__ float g_c1   [S];
__device__ float g_bqk  [(long)T * S * B];
__device__ float g_vu   [(long)T * S * B];

__device__ __forceinline__ float sigf(float x) { return 1.f / (1.f + __expf(-x)); }

__device__ __forceinline__ unsigned f2tf(float f) {
    unsigned u;
    asm("cvt.rna.tf32.f32 %0, %1;" : "=r"(u) : "f"(f));
    return u;
}

__device__ __forceinline__ void mma_tf32(float c[4],
    unsigned a0, unsigned a1, unsigned a2, unsigned a3,
    unsigned b0, unsigned b1)
{
    asm volatile(
        "mma.sync.aligned.m16n8k8.row.col.f32.tf32.tf32.f32 "
        "{%0,%1,%2,%3}, {%4,%5,%6,%7}, {%8,%9}, {%0,%1,%2,%3};"
        : "+f"(c[0]), "+f"(c[1]), "+f"(c[2]), "+f"(c[3])
        : "r"(a0), "r"(a1), "r"(a2), "r"(a3), "r"(b0), "r"(b1));
}

__device__ __forceinline__ void mma_f16(float c[4],
    unsigned a0, unsigned a1, unsigned a2, unsigned a3,
    unsigned b0, unsigned b1)
{
    asm volatile(
        "mma.sync.aligned.m16n8k16.row.col.f32.f16.f16.f32 "
        "{%0,%1,%2,%3}, {%4,%5,%6,%7}, {%8,%9}, {%0,%1,%2,%3};"
        : "+f"(c[0]), "+f"(c[1]), "+f"(c[2]), "+f"(c[3])
        : "r"(a0), "r"(a1), "r"(a2), "r"(a3), "r"(b0), "r"(b1));
}

__device__ __forceinline__ unsigned sptr(const void* p) {
    return (unsigned)__cvta_generic_to_shared(p);
}
__device__ __forceinline__ void cp16(void* s, const void* g) {
    asm volatile("cp.async.cg.shared.global [%0], [%1], 16;" :: "r"(sptr(s)), "l"(g));
}

// ---------------- prep ----------------
__global__ void prep_kernel(const float* __restrict__ x, const float* __restrict__ tgt) {
    int i = blockIdx.x * blockDim.x + threadIdx.x;
    if (i < S * B * H) { g_h16A[i] = __float2half(0.f); g_c[i] = 0.f; }
    if (i < L * B) {
        int l = i / B, b = i % B;
        g_inp[i] = (l == 0) ? x[(long)b * 96 * F + 95 * F + 0]
                            : tgt[(long)b * L + (l - 1)];
    }
}

// ---------------- weight conversion: f32 [s][4H][H] -> fp16 gate-interleaved ----
__global__ void conv_w16(const float* __restrict__ W, __half* __restrict__ dst) {
    long i = (long)blockIdx.x * 256 + threadIdx.x;   // over S*8*128*256
    int k = i & 255;
    long rr = i >> 8;
    int r = rr & 127;
    long jj_ = rr >> 7;
    int jb = jj_ & 7;
    int s = (int)(jj_ >> 3);
    int q = (r >> 3) & 3;
    int jloc = (r & 7) + ((r >> 5) << 3);
    dst[i] = __float2half(W[(long)s * G * H + (q * H + jb * 32 + jloc) * (long)H + k]);
}

// ---------------- warp-parallel precomputes ----------------
// warp per t in [0, S*H): u, wbqk, k2b
__global__ void pc_a(const float* __restrict__ Wout, const float* __restrict__ Wfcout,
                     const float* __restrict__ Win,  const float* __restrict__ b_in) {
    int gw = (blockIdx.x * blockDim.x + threadIdx.x) >> 5;
    int lane = threadIdx.x & 31;
    if (gw >= S * H) return;
    int s = gw >> 8, e = gw & 255;
    const float* wf2 = Wfcout + s * 2 * H + H;
    const float* Wo  = Wout + (long)s * H * H;
    const float* bq = b_in + s * 3 * H;
    const float* bk = bq + H;
    const float* Wq = Win + (long)s * 3 * H * H;
    const float* Wk = Wq + H * H;
    float u = 0.f, wb = 0.f, kb = 0.f;
#pragma unroll
    for (int i = 0; i < 8; i++) {
        int o = lane + i * 32;
        u  += wf2[o] * Wo[o * H + e];
        wb += bq[o]  * Wk[o * H + e];
        kb += Wq[o * H + e] * bk[o];
    }
#pragma unroll
    for (int off = 16; off; off >>= 1) {
        u  += __shfl_xor_sync(0xffffffffu, u, off);
        wb += __shfl_xor_sync(0xffffffffu, wb, off);
        kb += __shfl_xor_sync(0xffffffffu, kb, off);
    }
    if (lane == 0) { g_u[gw] = u; g_wbqk[gw] = wb; g_k2b[gw] = kb; }
}

// warp per t: wvu (needs g_u)
__global__ void pc_b(const float* __restrict__ Win) {
    int gw = (blockIdx.x * blockDim.x + threadIdx.x) >> 5;
    int lane = threadIdx.x & 31;
    if (gw >= S * H) return;
    int s = gw >> 8, h = gw & 255;
    const float* Wv = Win + (long)s * 3 * H * H + 2 * H * H;
    float wv = 0.f;
#pragma unroll
    for (int i = 0; i < 8; i++) {
        int e = lane + i * 32;
        wv += g_u[s * H + e] * Wv[e * H + h];
    }
#pragma unroll
    for (int off = 16; off; off >>= 1) wv += __shfl_xor_sync(0xffffffffu, wv, off);
    if (lane == 0) g_wvu[gw] = wv;
}

// warp per s: scalar constants (needs g_u)
__global__ void pc_c(const float* __restrict__ b_in, const float* __restrict__ Wfcout,
                     const float* __restrict__ b_fcout, const float* __restrict__ b_out) {
    int s = threadIdx.x >> 5;
    int lane = threadIdx.x & 31;
    if (s >= S) return;
    const float* bq = b_in + s * 3 * H;
    const float* bk = bq + H;
    const float* bv = bq + 2 * H;
    const float* wf2 = Wfcout + s * 2 * H + H;
    const float* bo  = b_out + s * H;
    float cvu = 0.f, cb = 0.f, c1 = 0.f;
#pragma unroll
    for (int i = 0; i < 8; i++) {
        int e = lane + i * 32;
        cvu += g_u[s * H + e] * bv[e];
        cb  += bq[e] * bk[e];
        c1  += wf2[e] * bo[e];
    }
#pragma unroll
    for (int off = 16; off; off >>= 1) {
        cvu += __shfl_xor_sync(0xffffffffu, cvu, off);
        cb  += __shfl_xor_sync(0xffffffffu, cb, off);
        c1  += __shfl_xor_sync(0xffffffffu, c1, off);
    }
    if (lane == 0) { g_cvu[s] = cvu; g_cbqk[s] = cb; g_c1[s] = c1 + b_fcout[s]; }
}

__global__ void pc_m1(const float* __restrict__ Win) {
    __shared__ float tq[16][17];
    __shared__ float tk[16][17];
    int s = blockIdx.z;
    const float* Wq = Win + (long)s * 3 * H * H;
    const float* Wk = Wq + H * H;
    int tyy = threadIdx.y, txx = threadIdx.x;
    int hq = blockIdx.y * 16 + tyy;
    int hk = blockIdx.x * 16 + txx;
    float acc = 0.f;
    for (int e0 = 0; e0 < H; e0 += 16) {
        tq[tyy][txx] = Wq[(e0 + tyy) * H + blockIdx.y * 16 + txx];
        tk[tyy][txx] = Wk[(e0 + tyy) * H + hk];
        __syncthreads();
#pragma unroll
        for (int ee = 0; ee < 16; ee++)
            acc = fmaf(tq[ee][tyy], tk[ee][txx], acc);
        __syncthreads();
    }
    g_M1[(long)s * H * H + hq * H + hk] = acc;
}

// ================= generic tf32 tensor-core GEMM (f32 or fp16 out) =========
__global__ void __launch_bounds__(256) gemm_tc(
    const float* __restrict__ Ag, long sAz, int lda,
    const float* __restrict__ Wg, long sWz, int ldw,
    const float* __restrict__ b1, const float* __restrict__ b2, long sBz,
    float* __restrict__ C, __half* __restrict__ Ch, long sCz, int ldc,
    int K, int wdiv)
{
    __shared__ unsigned As[2][128 * 20];
    __shared__ unsigned Ws[2][128 * 20];

    const int z  = blockIdx.z;
    const int wi = (z / wdiv) & 7;
    const int m0 = blockIdx.y * 128;
    const int n0 = blockIdx.x * 128;

    const float* Ap = Ag + (long)z * sAz + (long)m0 * lda;
    const float* Wp = Wg + (long)wi * sWz + (long)n0 * ldw;

    const int t = threadIdx.x;
    const int w = t >> 5, lane = t & 31;
    const int lq = lane >> 2, lr = lane & 3;
    const int wm = w & 3, wn = w >> 2;

    float4 pa[2], pw[2];

    auto ld = [&](int c) {
        int k0 = c * 16;
#pragma unroll
        for (int p = 0; p < 2; p++) {
            int i = t + 256 * p;
            int row = i >> 2, k4 = i & 3;
            int k = k0 + k4 * 4;
            if (k < K) {
                pa[p] = *(const float4*)(Ap + (long)row * lda + k);
                pw[p] = *(const float4*)(Wp + (long)row * ldw + k);
            } else {
                pa[p] = make_float4(0.f, 0.f, 0.f, 0.f);
                pw[p] = make_float4(0.f, 0.f, 0.f, 0.f);
            }
        }
    };
    auto st = [&](int bf) {
#pragma unroll
        for (int p = 0; p < 2; p++) {
            int i = t + 256 * p;
            int row = i >> 2, k4 = i & 3;
            uint4 ua = make_uint4(f2tf(pa[p].x), f2tf(pa[p].y), f2tf(pa[p].z), f2tf(pa[p].w));
            uint4 uw = make_uint4(f2tf(pw[p].x), f2tf(pw[p].y), f2tf(pw[p].z), f2tf(pw[p].w));
            *(uint4*)&As[bf][row * 20 + k4 * 4] = ua;
            *(uint4*)&Ws[bf][row * 20 + k4 * 4] = uw;
        }
    };

    float acc[2][8][4];
#pragma unroll
    for (int mt = 0; mt < 2; mt++)
#pragma unroll
        for (int nt = 0; nt < 8; nt++)
#pragma unroll
            for (int v = 0; v < 4; v++) acc[mt][nt][v] = 0.f;

    const int NC = (K + 15) / 16;
    ld(0); st(0);
    __syncthreads();

    for (int c = 0; c < NC; c++) {
        int cur = c & 1;
        if (c + 1 < NC) ld(c + 1);
#pragma unroll
        for (int k8s = 0; k8s < 2; k8s++) {
            int kb = k8s * 8;
            unsigned a[2][4];
#pragma unroll
            for (int mt = 0; mt < 2; mt++) {
                int r = wm * 32 + mt * 16 + lq;
                a[mt][0] = As[cur][r * 20 + kb + lr];
                a[mt][1] = As[cur][(r + 8) * 20 + kb + lr];
                a[mt][2] = As[cur][r * 20 + kb + lr + 4];
                a[mt][3] = As[cur][(r + 8) * 20 + kb + lr + 4];
            }
#pragma unroll
            for (int nt = 0; nt < 8; nt++) {
                int rn = wn * 64 + nt * 8 + lq;
                unsigned bb0 = Ws[cur][rn * 20 + kb + lr];
                unsigned bb1 = Ws[cur][rn * 20 + kb + lr + 4];
#pragma unroll
                for (int mt = 0; mt < 2; mt++)
                    mma_tf32(acc[mt][nt], a[mt][0], a[mt][1], a[mt][2], a[mt][3], bb0, bb1);
            }
        }
        if (c + 1 < NC) st(cur ^ 1);
        __syncthreads();
    }

#pragma unroll
    for (int mt = 0; mt < 2; mt++) {
#pragma unroll
        for (int nt = 0; nt < 8; nt++) {
#pragma unroll
            for (int rh = 0; rh < 2; rh++) {
                int m = m0 + wm * 32 + mt * 16 + lq + rh * 8;
                int n = n0 + wn * 64 + nt * 8 + lr * 2;
                float v0 = acc[mt][nt][rh * 2];
                float v1 = acc[mt][nt][rh * 2 + 1];
                if (b1) { v0 += b1[(long)wi * sBz + n]; v1 += b1[(long)wi * sBz + n + 1]; }
                if (b2) { v0 += b2[(long)wi * sBz + n]; v1 += b2[(long)wi * sBz + n + 1]; }
                if (Ch)
                    *(__half2*)&Ch[(long)z * sCz + (long)m * ldc + n] = __floats2half2_rn(v0, v1);
                else
                    *(float2*)&C[(long)z * sCz + (long)m * ldc + n] = make_float2(v0, v1);
            }
        }
    }
}

// ---------------- shared attention device function (fp16 h, fp16 k2) --------
__device__ __forceinline__ void attn_one(const __half* __restrict__ hbase, int sb, int lane,
                                         const float* __restrict__ Wfcout, int lstep)
{
    int ss = sb >> 10;
    const __half2* hp2 = (const __half2*)(hbase + (long)sb * H);
    float2 hf[4];
    {
        __half2 v0 = hp2[lane * 2], v1 = hp2[lane * 2 + 1];
        __half2 v2 = hp2[64 + lane * 2], v3 = hp2[65 + lane * 2];
        hf[0] = __half22float2(v0); hf[1] = __half22float2(v1);
        hf[2] = __half22float2(v2); hf[3] = __half22float2(v3);
    }
    const float* wf = Wfcout + ss * 2 * H;
    float4 w0 = *(const float4*)&wf[lane * 4];
    float4 w1 = *(const float4*)&wf[128 + lane * 4];

    float red[T + 1];
    red[T] = hf[0].x * w0.x + hf[0].y * w0.y + hf[1].x * w0.z + hf[1].y * w0.w
           + hf[2].x * w1.x + hf[2].y * w1.y + hf[3].x * w1.z + hf[3].y * w1.w;
#pragma unroll
    for (int tt = 0; tt < T; tt++) {
        const __half2* kp2 = (const __half2*)(g_k2h + ((long)tt * S * B + sb) * H);
        float2 k0 = __half22float2(kp2[lane * 2]);
        float2 k1 = __half22float2(kp2[lane * 2 + 1]);
        float2 k2_ = __half22float2(kp2[64 + lane * 2]);
        float2 k3 = __half22float2(kp2[65 + lane * 2]);
        red[tt] = hf[0].x * k0.x + hf[0].y * k0.y + hf[1].x * k1.x + hf[1].y * k1.y
                + hf[2].x * k2_.x + hf[2].y * k2_.y + hf[3].x * k3.x + hf[3].y * k3.y;
    }
#pragma unroll
    for (int r = 0; r < T + 1; r++) {
        float v = red[r];
#pragma unroll
        for (int off = 16; off; off >>= 1) v += __shfl_xor_sync(0xffffffffu, v, off);
        red[r] = v;
    }
    float sc[T];
    float mx = -1e30f;
#pragma unroll
    for (int tt = 0; tt < T; tt++) {
        float v = (red[tt] + g_bqk[(long)tt * S * B + sb]) * 0.0625f;
        sc[tt] = v;
        mx = fmaxf(mx, v);
    }
    float sum = 0.f;
#pragma unroll
    for (int tt = 0; tt < T; tt++) { sc[tt] = __expf(sc[tt] - mx); sum += sc[tt]; }
    float inv = 1.f / sum;
    float ctxdot = 0.f;
#pragma unroll
    for (int tt = 0; tt < T; tt++)
        ctxdot = fmaf(sc[tt] * inv, g_vu[(long)tt * S * B + sb], ctxdot);
    if (lane == 0)
        g_outs[(long)lstep * S * B + sb] = red[T] + ctxdot + g_c1[ss];
}

// ============ fp16 fused step kernel, single wave (256 blocks) ==============
// grid (4,8,8): x = j-block pair (64 j), y = 128 b-rows, z = s.
// A tile (128x256 fp16) staged ONCE in smem; two 128-col n-tiles (jblk=bx*2+hh)
// processed sequentially with double-buffered Ws. LSTM in epilogue per half.
template <int DEC>
__global__ void __launch_bounds__(256, 2) step16_k(
    const __half* __restrict__ hin, __half* __restrict__ hout,
    const __half* __restrict__ W16,
    const float* __restrict__ b1, const float* __restrict__ b2,
    const float* __restrict__ cvec,
    const float* __restrict__ add, long sAddz,
    float* __restrict__ encout,
    const float* __restrict__ Wfcout,
    int itstep, int lstep)
{
    extern __shared__ __align__(16) __half smem[];
    __half* As = smem;                       // 128 * PA
    __half* Ws = smem + 128 * PA;            // 2 * 128 * PH

    const int s  = blockIdx.z;
    const int m0 = blockIdx.y * 128;

    const __half* Aph = hin + ((long)s * B + m0) * H;

    const int t = threadIdx.x;
    const int w = t >> 5, lane = t & 31;
    const int lq = lane >> 2, lr = lane & 3;
    const int wm = w & 3, wn = w >> 2;

    auto issueW = [&](const __half* Wph, int cidx, int buf) {
#pragma unroll
        for (int p = 0; p < 2; p++) {
            int idx = t + 256 * p;
            int row = idx >> 2, seg = idx & 3;
            cp16(&Ws[buf * 128 * PH + row * PH + seg * 8],
                 Wph + (long)row * H + cidx * 32 + seg * 8);
        }
    };

    // prologue: stage full A tile + Ws(half0, chunk0) in one group
    {
#pragma unroll
        for (int p = 0; p < 16; p++) {
            int idx = t + 256 * p;
            int row = idx >> 5, seg = idx & 31;
            cp16(&As[row * PA + seg * 8], Aph + (long)row * H + seg * 8);
        }
        const __half* Wph0 = W16 + ((long)(s * 8 + blockIdx.x * 2) * 128) * H;
        issueW(Wph0, 0, 0);
        asm volatile("cp.async.commit_group;");
    }

#pragma unroll 1
    for (int hh = 0; hh < 2; hh++) {
        const int jblk = blockIdx.x * 2 + hh;
        const __half* Wph = W16 + ((long)(s * 8 + jblk) * 128) * H;
        if (hh == 1) {
            issueW(Wph, 0, 0);
            asm volatile("cp.async.commit_group;");
        }

        float acc[2][8][4];
#pragma unroll
        for (int mt = 0; mt < 2; mt++)
#pragma unroll
            for (int nt = 0; nt < 8; nt++)
#pragma unroll
                for (int v = 0; v < 4; v++) acc[mt][nt][v] = 0.f;

#pragma unroll 1
        for (int c = 0; c < 8; c++) {
            if (c < 7) {
                issueW(Wph, c + 1, (c + 1) & 1);
                asm volatile("cp.async.commit_group;");
                asm volatile("cp.async.wait_group 1;");
            } else {
                asm volatile("cp.async.wait_group 0;");
            }
            __syncthreads();
            int buf = c & 1;
            const __half* Wsb = Ws + buf * 128 * PH;
#pragma unroll
            for (int k16 = 0; k16 < 2; k16++) {
                int ka = c * 32 + k16 * 16;   // A k-offset in full tile
                int kb = k16 * 16;            // Ws k-offset in chunk
                unsigned a[2][4];
#pragma unroll
                for (int mt = 0; mt < 2; mt++) {
                    int r = wm * 32 + mt * 16 + lq;
                    a[mt][0] = *(const unsigned*)&As[r * PA + ka + lr * 2];
                    a[mt][1] = *(const unsigned*)&As[(r + 8) * PA + ka + lr * 2];
                    a[mt][2] = *(const unsigned*)&As[r * PA + ka + 8 + lr * 2];
                    a[mt][3] = *(const unsigned*)&As[(r + 8) * PA + ka + 8 + lr * 2];
                }
#pragma unroll
                for (int nt = 0; nt < 8; nt++) {
                    int rn = wn * 64 + nt * 8 + lq;
                    unsigned bb0 = *(const unsigned*)&Wsb[rn * PH + kb + lr * 2];
                    unsigned bb1 = *(const unsigned*)&Wsb[rn * PH + kb + 8 + lr * 2];
#pragma unroll
                    for (int mt = 0; mt < 2; mt++)
                        mma_f16(acc[mt][nt], a[mt][0], a[mt][1], a[mt][2], a[mt][3], bb0, bb1);
                }
            }
            __syncthreads();
        }

        // ---- epilogue for this half: j0 = bx*64 + hh*32 ----
        const int j0 = blockIdx.x * 64 + hh * 32;
#pragma unroll
        for (int mt = 0; mt < 2; mt++) {
#pragma unroll
            for (int rh = 0; rh < 2; rh++) {
                int b_row = m0 + wm * 32 + mt * 16 + lq + rh * 8;
                float rv = DEC ? g_inp[itstep * B + b_row] : 0.f;
#pragma unroll
                for (int d = 0; d < 2; d++) {
                    int j = j0 + (wn * 2 + d) * 8 + lr * 2;
                    float gate[4][2];
#pragma unroll
                    for (int q = 0; q < 4; q++) {
                        int nt = d * 4 + q;
                        float v0 = acc[mt][nt][rh * 2];
                        float v1 = acc[mt][nt][rh * 2 + 1];
                        int gg = q * H + j;
                        if (DEC) {
                            float2 x1 = *(const float2*)&b1[s * G + gg];
                            float2 x2 = *(const float2*)&b2[s * G + gg];
                            float2 xc = *(const float2*)&cvec[s * G + gg];
                            v0 += x1.x + x2.x + rv * xc.x;
                            v1 += x1.y + x2.y + rv * xc.y;
                        } else {
                            float2 xa = *(const float2*)&add[(long)s * sAddz + (long)b_row * G + gg];
                            v0 += xa.x; v1 += xa.y;
                        }
                        gate[q][0] = v0; gate[q][1] = v1;
                    }
                    long base = ((long)s * B + b_row) * H + j;
                    float2 cold = *(const float2*)&g_c[base];
                    float co[2] = {cold.x, cold.y};
                    float hn[2], cn[2];
#pragma unroll
                    for (int dd = 0; dd < 2; dd++) {
                        float c_ = sigf(gate[1][dd]) * co[dd] + sigf(gate[0][dd]) * tanhf(gate[2][dd]);
                        cn[dd] = c_;
                        hn[dd] = sigf(gate[3][dd]) * tanhf(c_);
                    }
                    *(float2*)&g_c[base] = make_float2(cn[0], cn[1]);
                    *(__half2*)&hout[base] = __floats2half2_rn(hn[0], hn[1]);
                    if (!DEC) *(float2*)&encout[base] = make_float2(hn[0], hn[1]);
                }
            }
        }
    }

    // ---- fused attention for step lstep (reads hin = h16(lstep)) ----
    if (DEC && lstep >= 0) {
        int bid = (blockIdx.z * 8 + blockIdx.y) * 4 + blockIdx.x;   // 0..255
        int gw = bid * 8 + w;                                        // 2048 warps
#pragma unroll 1
        for (int rep = 0; rep < 4; rep++)
            attn_one(hin, gw + rep * 2048, lane, Wfcout, lstep);
    }
}

// ---------------- per-(t,s,b) scalars ----------------
__global__ void pc_scal_kernel() {
    int gtid = blockIdx.x * blockDim.x + threadIdx.x;
    int warp = gtid >> 5;
    int lane = threadIdx.x & 31;
    if (warp >= T * S * B) return;
    int s = (warp >> 10) & 7;

    const float* ep = g_enc + (long)warp * H;
    const float* wb = g_wbqk + s * H;
    const float* wv = g_wvu + s * H;
    float db = 0.f, dv = 0.f;
#pragma unroll
    for (int u = 0; u < 2; u++) {
        int e = lane * 4 + u * 128;
        float4 ev = *(const float4*)&ep[e];
        float4 b4 = *(const float4*)&wb[e];
        float4 v4 = *(const float4*)&wv[e];
        db += ev.x * b4.x + ev.y * b4.y + ev.z * b4.z + ev.w * b4.w;
        dv += ev.x * v4.x + ev.y * v4.y + ev.z * v4.z + ev.w * v4.w;
    }
#pragma unroll
    for (int off = 16; off; off >>= 1) {
        db += __shfl_xor_sync(0xffffffffu, db, off);
        dv += __shfl_xor_sync(0xffffffffu, dv, off);
    }
    if (lane == 0) {
        g_bqk[warp] = db + g_cbqk[s];
        g_vu[warp]  = dv + g_cvu[s];
    }
}

// ---------------- standalone attention (last decoder step) ----------------
__global__ void dec_attn_kernel(const __half* __restrict__ hcur,
                                const float* __restrict__ Wfcout, int l) {
    int gtid = blockIdx.x * blockDim.x + threadIdx.x;
    int warp = gtid >> 5;
    int lane = threadIdx.x & 31;
    if (warp >= S * B) return;
    attn_one(hcur, warp, lane, Wfcout, l);
}

// ---------------- final 8->1 mix ----------------
__global__ void final_kernel(const float* __restrict__ Wfc, const float* __restrict__ bfc,
                             float* __restrict__ out) {
    int i = blockIdx.x * blockDim.x + threadIdx.x;
    if (i >= B * L) return;
    int b = i / L, l = i % L;
    float acc = bfc[0];
#pragma unroll
    for (int s = 0; s < S; s++)
        acc += g_outs[(long)l * S * B + (long)s * B + b] * Wfc[s];
    out[i] = acc;
}

// ---------------- host launch ----------------
extern "C" void kernel_launch(void* const* d_in, const int* in_sizes, int n_in,
                              void* d_out, int out_size) {
    const float* x       = (const float*)d_in[0];
    const float* tgt     = (const float*)d_in[1];
    const float* W_ih_e  = (const float*)d_in[2];
    const float* W_hh_e  = (const float*)d_in[3];
    const float* b_ih_e  = (const float*)d_in[4];
    const float* b_hh_e  = (const float*)d_in[5];
    const float* W_ih_d  = (const float*)d_in[6];
    const float* W_hh_d  = (const float*)d_in[7];
    const float* b_ih_d  = (const float*)d_in[8];
    const float* b_hh_d  = (const float*)d_in[9];
    const float* W_in    = (const float*)d_in[10];
    const float* b_in    = (const float*)d_in[11];
    const float* W_out   = (const float*)d_in[12];
    const float* b_out   = (const float*)d_in[13];
    const float* W_fcout = (const float*)d_in[14];
    const float* b_fcout = (const float*)d_in[15];
    const float* W_fc    = (const float*)d_in[16];
    const float* b_fc    = (const float*)d_in[17];
    float* out = (float*)d_out;

    float *Gin, *enc, *M1, *k2b;
    __half *h16[2], *W16e, *W16d, *k2h;
    cudaGetSymbolAddress((void**)&Gin, g_Gin);
    cudaGetSymbolAddress((void**)&enc, g_enc);
    cudaGetSymbolAddress((void**)&k2h, g_k2h);
    cudaGetSymbolAddress((void**)&M1,  g_M1);
    cudaGetSymbolAddress((void**)&k2b, g_k2b);
    cudaGetSymbolAddress((void**)&h16[0], g_h16A);
    cudaGetSymbolAddress((void**)&h16[1], g_h16B);
    cudaGetSymbolAddress((void**)&W16e, g_W16e);
    cudaGetSymbolAddress((void**)&W16d, g_W16d);

    static int smem_set = 0;
    if (!smem_set) {
        cudaFuncSetAttribute(step16_k<0>, cudaFuncAttributeMaxDynamicSharedMemorySize, STEP_SMEM);
        cudaFuncSetAttribute(step16_k<1>, cudaFuncAttributeMaxDynamicSharedMemorySize, STEP_SMEM);
        smem_set = 1;
    }

    prep_kernel<<<(S * B * H + 255) / 256, 256>>>(x, tgt);
    conv_w16<<<(int)((long)S * G * H / 256), 256>>>(W_hh_e, W16e);
    conv_w16<<<(int)((long)S * G * H / 256), 256>>>(W_hh_d, W16d);
    pc_a<<<S * H * 32 / 256, 256>>>(W_out, W_fcout, W_in, b_in);
    pc_b<<<S * H * 32 / 256, 256>>>(W_in);
    pc_c<<<1, 256>>>(b_in, W_fcout, b_fcout, b_out);
    pc_m1<<<dim3(16, 16, 8), dim3(16, 16)>>>(W_in);

    // 1) encoder input projections (biases folded): Gin[z=s*12+t][b][g]
    gemm_tc<<<dim3(G / 128, B / 128, 96), 256>>>(
        x, (long)F, 96 * F,
        W_ih_e, (long)G * F, F,
        b_ih_e, b_hh_e, G,
        Gin, nullptr, (long)B * G, G, F, 12);

    // 2) encoder recurrence: h16 ping-pong, f32 copy -> g_enc[t]
    const dim3 sgrid(4, 8, 8);
    for (int tt = 0; tt < T; tt++) {
        step16_k<0><<<sgrid, 256, STEP_SMEM>>>(
            h16[tt & 1], h16[(tt + 1) & 1], W16e,
            nullptr, nullptr, nullptr,
            Gin + (long)tt * B * G, 12l * B * G,
            enc + (long)tt * S * B * H,
            nullptr, 0, -1);
    }

    // 3) per-key scalars + transformed keys (fp16 out)
    pc_scal_kernel<<<(T * S * B * 32 + 255) / 256, 256>>>();
    gemm_tc<<<dim3(H / 128, B / 128, T * S), 256>>>(
        enc, (long)B * H, H,
        M1, (long)H * H, H,
        k2b, nullptr, H,
        nullptr, k2h, (long)B * H, H, H, 1);

    // 4) decoder: gates(l) + fused attention(l-1)
    for (int l = 0; l < L; l++) {
        step16_k<1><<<sgrid, 256, STEP_SMEM>>>(
            h16[l & 1], h16[(l + 1) & 1], W16d,
            b_ih_d, b_hh_d, W_ih_d,
            nullptr, 0,
            nullptr,
            W_fcout, l, l - 1);
    }
    dec_attn_kernel<<<(S * B * 32 + 255) / 256, 256>>>(h16[L & 1], W_fcout, L - 1);

    // 5) final mix
    final_kernel<<<(B * L + 255) / 256, 256>>>(W_fc, b_fc, out);
}

// round 9
// speedup vs baseline: 2.1175x; 1.1368x over previous
#include <cuda_runtime.h>
#include <cuda_fp16.h>
#include <math.h>

// ---------------- problem constants ----------------
#define S   8
#define T   12
#define H   256
#define F   316
#define B   1024
#define L   48
#define G   1024      // 4*H
#define KX  320       // padded K for input projection (>=F, mult of 32)
#define PH  40        // Ws smem pitch (halves)
#define PA  264       // A-full smem pitch (halves)
#define NBP 256       // persistent grid size
#define SBH (S * B * H)
#define STEP_SMEM (128 * PA * 2 + 2 * 128 * PH * 2)   // 88064 B

// ---------------- scratch (device globals; no allocs allowed) ----------------
__device__ __half g_Gin16[96l * B * G];          // encoder input gates fp16
__device__ __half g_x16[(long)B * 96 * KX];      // x fp16, zero-padded rows
__device__ __half g_W16ih[(long)S * G * KX];     // W_ih_e fp16, padded
__device__ __half g_enc16[(long)T * SBH];        // encoder outputs fp16
__device__ __half g_k2h[(long)T * SBH];          // transformed keys fp16
__device__ __half g_h16A[SBH];                   // decoder h ping-pong / zero seed
__device__ __half g_h16B[SBH];
__device__ __half g_W16e[(long)S * G * H];       // enc W_hh fp16, gate-interleaved
__device__ __half g_W16d[(long)S * G * H];       // dec W_hh fp16, gate-interleaved
__device__ __half g_M1h[S * H * H];              // Wq^T @ Wk fp16
__device__ float  g_c  [SBH];
__device__ float  g_inp[L * B];
__device__ float  g_outs[(long)L * S * B];
__device__ float g_u    [S * H];
__device__ float g_wbqk [S * H];
__device__ float g_wvu  [S * H];
__device__ float g_k2b  [S * H];
__device__ float g_cbqk [S];
__device__ float g_cvu  [S];
__device__ float g_c1   [S];
__device__ float g_bqk  [(long)T * S * B];
__device__ float g_vu   [(long)T * S * B];
__device__ unsigned g_bar;                       // gen<<16 | count

__device__ __forceinline__ float sigf(float x) { return 1.f / (1.f + __expf(-x)); }

__device__ __forceinline__ void mma_f16(float c[4],
    unsigned a0, unsigned a1, unsigned a2, unsigned a3,
    unsigned b0, unsigned b1)
{
    asm volatile(
        "mma.sync.aligned.m16n8k16.row.col.f32.f16.f16.f32 "
        "{%0,%1,%2,%3}, {%4,%5,%6,%7}, {%8,%9}, {%0,%1,%2,%3};"
        : "+f"(c[0]), "+f"(c[1]), "+f"(c[2]), "+f"(c[3])
        : "r"(a0), "r"(a1), "r"(a2), "r"(a3), "r"(b0), "r"(b1));
}

__device__ __forceinline__ unsigned sptr(const void* p) {
    return (unsigned)__cvta_generic_to_shared(p);
}
__device__ __forceinline__ void cp16(void* s, const void* g) {
    asm volatile("cp.async.cg.shared.global [%0], [%1], 16;" :: "r"(sptr(s)), "l"(g));
}

// single-word generation grid barrier (all NBP blocks resident by construction)
__device__ __forceinline__ void grid_bar() {
    __syncthreads();
    if (threadIdx.x == 0) {
        __threadfence();
        unsigned old = atomicAdd(&g_bar, 1u);
        unsigned gen = old >> 16;
        if ((old & 0xffffu) == NBP - 1)
            atomicAdd(&g_bar, 0x10000u - NBP);
        while ((*(volatile unsigned*)&g_bar) >> 16 == gen) __nanosleep(64);
        __threadfence();
    }
    __syncthreads();
}

// ---------------- prep & conversions ----------------
__global__ void prep_kernel(const float* __restrict__ x, const float* __restrict__ tgt) {
    int i = blockIdx.x * blockDim.x + threadIdx.x;
    if (i < SBH) { g_h16A[i] = __float2half(0.f); g_c[i] = 0.f; }
    if (i < L * B) {
        int l = i / B, b = i % B;
        g_inp[i] = (l == 0) ? x[(long)b * 96 * F + 95 * F + 0]
                            : tgt[(long)b * L + (l - 1)];
    }
}

__global__ void conv_x16(const float* __restrict__ x) {
    long i = (long)blockIdx.x * 256 + threadIdx.x;
    if (i >= (long)B * 96 * KX) return;
    int k = (int)(i % KX);
    long br = i / KX;
    g_x16[i] = (k < F) ? __float2half(x[br * F + k]) : __float2half(0.f);
}

__global__ void conv_wih(const float* __restrict__ Wf) {
    long i = (long)blockIdx.x * 256 + threadIdx.x;
    if (i >= (long)S * G * KX) return;
    int k = (int)(i % KX);
    long sg = i / KX;
    g_W16ih[i] = (k < F) ? __float2half(Wf[sg * F + k]) : __float2half(0.f);
}

// W_hh f32 [s][4H][H] -> fp16 gate-interleaved [s][jblk][128][256]
__global__ void conv_w16(const float* __restrict__ W, __half* __restrict__ dst) {
    long i = (long)blockIdx.x * 256 + threadIdx.x;
    int k = i & 255;
    long rr = i >> 8;
    int r = rr & 127;
    long jj_ = rr >> 7;
    int jb = jj_ & 7;
    int s = (int)(jj_ >> 3);
    int q = (r >> 3) & 3;
    int jloc = (r & 7) + ((r >> 5) << 3);
    dst[i] = __float2half(W[(long)s * G * H + (q * H + jb * 32 + jloc) * (long)H + k]);
}

// ---------------- warp-parallel precomputes ----------------
__global__ void pc_a(const float* __restrict__ Wout, const float* __restrict__ Wfcout,
                     const float* __restrict__ Win,  const float* __restrict__ b_in) {
    int gw = (blockIdx.x * blockDim.x + threadIdx.x) >> 5;
    int lane = threadIdx.x & 31;
    if (gw >= S * H) return;
    int s = gw >> 8, e = gw & 255;
    const float* wf2 = Wfcout + s * 2 * H + H;
    const float* Wo  = Wout + (long)s * H * H;
    const float* bq = b_in + s * 3 * H;
    const float* bk = bq + H;
    const float* Wq = Win + (long)s * 3 * H * H;
    const float* Wk = Wq + H * H;
    float u = 0.f, wb = 0.f, kb = 0.f;
#pragma unroll
    for (int i = 0; i < 8; i++) {
        int o = lane + i * 32;
        u  += wf2[o] * Wo[o * H + e];
        wb += bq[o]  * Wk[o * H + e];
        kb += Wq[o * H + e] * bk[o];
    }
#pragma unroll
    for (int off = 16; off; off >>= 1) {
        u  += __shfl_xor_sync(0xffffffffu, u, off);
        wb += __shfl_xor_sync(0xffffffffu, wb, off);
        kb += __shfl_xor_sync(0xffffffffu, kb, off);
    }
    if (lane == 0) { g_u[gw] = u; g_wbqk[gw] = wb; g_k2b[gw] = kb; }
}

__global__ void pc_b(const float* __restrict__ Win) {
    int gw = (blockIdx.x * blockDim.x + threadIdx.x) >> 5;
    int lane = threadIdx.x & 31;
    if (gw >= S * H) return;
    int s = gw >> 8, h = gw & 255;
    const float* Wv = Win + (long)s * 3 * H * H + 2 * H * H;
    float wv = 0.f;
#pragma unroll
    for (int i = 0; i < 8; i++) {
        int e = lane + i * 32;
        wv += g_u[s * H + e] * Wv[e * H + h];
    }
#pragma unroll
    for (int off = 16; off; off >>= 1) wv += __shfl_xor_sync(0xffffffffu, wv, off);
    if (lane == 0) g_wvu[gw] = wv;
}

__global__ void pc_c(const float* __restrict__ b_in, const float* __restrict__ Wfcout,
                     const float* __restrict__ b_fcout, const float* __restrict__ b_out) {
    int s = threadIdx.x >> 5;
    int lane = threadIdx.x & 31;
    if (s >= S) return;
    const float* bq = b_in + s * 3 * H;
    const float* bk = bq + H;
    const float* bv = bq + 2 * H;
    const float* wf2 = Wfcout + s * 2 * H + H;
    const float* bo  = b_out + s * H;
    float cvu = 0.f, cb = 0.f, c1 = 0.f;
#pragma unroll
    for (int i = 0; i < 8; i++) {
        int e = lane + i * 32;
        cvu += g_u[s * H + e] * bv[e];
        cb  += bq[e] * bk[e];
        c1  += wf2[e] * bo[e];
    }
#pragma unroll
    for (int off = 16; off; off >>= 1) {
        cvu += __shfl_xor_sync(0xffffffffu, cvu, off);
        cb  += __shfl_xor_sync(0xffffffffu, cb, off);
        c1  += __shfl_xor_sync(0xffffffffu, c1, off);
    }
    if (lane == 0) { g_cvu[s] = cvu; g_cbqk[s] = cb; g_c1[s] = c1 + b_fcout[s]; }
}

__global__ void pc_m1(const float* __restrict__ Win) {
    __shared__ float tq[16][17];
    __shared__ float tk[16][17];
    int s = blockIdx.z;
    const float* Wq = Win + (long)s * 3 * H * H;
    const float* Wk = Wq + H * H;
    int tyy = threadIdx.y, txx = threadIdx.x;
    int hq = blockIdx.y * 16 + tyy;
    int hk = blockIdx.x * 16 + txx;
    float acc = 0.f;
    for (int e0 = 0; e0 < H; e0 += 16) {
        tq[tyy][txx] = Wq[(e0 + tyy) * H + blockIdx.y * 16 + txx];
        tk[tyy][txx] = Wk[(e0 + tyy) * H + hk];
        __syncthreads();
#pragma unroll
        for (int ee = 0; ee < 16; ee++)
            acc = fmaf(tq[ee][tyy], tk[ee][txx], acc);
        __syncthreads();
    }
    g_M1h[(long)s * H * H + hq * H + hk] = __float2half(acc);
}

// ================= generic fp16 tensor-core GEMM (Gin, k2) ==================
// C[z][m][n] = sum_k A[z][m][k] * W[wi][n][k] (+b1+b2, f32) -> fp16
__global__ void __launch_bounds__(256) gemm_f16(
    const __half* __restrict__ Ag, long sAz, int lda,
    const __half* __restrict__ Wg, long sWz, int ldw,
    const float* __restrict__ b1, const float* __restrict__ b2, long sBz,
    __half* __restrict__ C, long sCz, int ldc,
    int NC, int wdiv)
{
    __shared__ __align__(16) __half As[2][128 * PH];
    __shared__ __align__(16) __half Ws[2][128 * PH];

    const int z  = blockIdx.z;
    const int wi = (z / wdiv) & 7;
    const int m0 = blockIdx.y * 128;
    const int n0 = blockIdx.x * 128;

    const __half* Ap = Ag + (long)z * sAz + (long)m0 * lda;
    const __half* Wp = Wg + (long)wi * sWz + (long)n0 * ldw;

    const int t = threadIdx.x;
    const int w = t >> 5, lane = t & 31;
    const int lq = lane >> 2, lr = lane & 3;
    const int wm = w & 3, wn = w >> 2;

    auto issue = [&](int c) {
        int buf = c & 1;
#pragma unroll
        for (int p = 0; p < 2; p++) {
            int idx = t + 256 * p;
            int row = idx >> 2, seg = idx & 3;
            cp16(&As[buf][row * PH + seg * 8], Ap + (long)row * lda + c * 32 + seg * 8);
            cp16(&Ws[buf][row * PH + seg * 8], Wp + (long)row * ldw + c * 32 + seg * 8);
        }
        asm volatile("cp.async.commit_group;");
    };

    float acc[2][8][4];
#pragma unroll
    for (int mt = 0; mt < 2; mt++)
#pragma unroll
        for (int nt = 0; nt < 8; nt++)
#pragma unroll
            for (int v = 0; v < 4; v++) acc[mt][nt][v] = 0.f;

    issue(0);

#pragma unroll 1
    for (int c = 0; c < NC; c++) {
        if (c < NC - 1) {
            issue(c + 1);
            asm volatile("cp.async.wait_group 1;");
        } else {
            asm volatile("cp.async.wait_group 0;");
        }
        __syncthreads();
        int buf = c & 1;
#pragma unroll
        for (int k16 = 0; k16 < 2; k16++) {
            int kb = k16 * 16;
            unsigned a[2][4];
#pragma unroll
            for (int mt = 0; mt < 2; mt++) {
                int r = wm * 32 + mt * 16 + lq;
                a[mt][0] = *(const unsigned*)&As[buf][r * PH + kb + lr * 2];
                a[mt][1] = *(const unsigned*)&As[buf][(r + 8) * PH + kb + lr * 2];
                a[mt][2] = *(const unsigned*)&As[buf][r * PH + kb + 8 + lr * 2];
                a[mt][3] = *(const unsigned*)&As[buf][(r + 8) * PH + kb + 8 + lr * 2];
            }
#pragma unroll
            for (int nt = 0; nt < 8; nt++) {
                int rn = wn * 64 + nt * 8 + lq;
                unsigned bb0 = *(const unsigned*)&Ws[buf][rn * PH + kb + lr * 2];
                unsigned bb1 = *(const unsigned*)&Ws[buf][rn * PH + kb + 8 + lr * 2];
#pragma unroll
                for (int mt = 0; mt < 2; mt++)
                    mma_f16(acc[mt][nt], a[mt][0], a[mt][1], a[mt][2], a[mt][3], bb0, bb1);
            }
        }
        __syncthreads();
    }

#pragma unroll
    for (int mt = 0; mt < 2; mt++) {
#pragma unroll
        for (int nt = 0; nt < 8; nt++) {
#pragma unroll
            for (int rh = 0; rh < 2; rh++) {
                int m = m0 + wm * 32 + mt * 16 + lq + rh * 8;
                int n = n0 + wn * 64 + nt * 8 + lr * 2;
                float v0 = acc[mt][nt][rh * 2];
                float v1 = acc[mt][nt][rh * 2 + 1];
                if (b1) { v0 += b1[(long)wi * sBz + n]; v1 += b1[(long)wi * sBz + n + 1]; }
                if (b2) { v0 += b2[(long)wi * sBz + n]; v1 += b2[(long)wi * sBz + n + 1]; }
                *(__half2*)&C[(long)z * sCz + (long)m * ldc + n] = __floats2half2_rn(v0, v1);
            }
        }
    }
}

// ---------------- shared attention device function (fp16 h, fp16 k2) --------
__device__ __forceinline__ void attn_one(const __half* __restrict__ hbase, int sb, int lane,
                                         const float* __restrict__ Wfcout, int lstep)
{
    int ss = sb >> 10;
    const __half2* hp2 = (const __half2*)(hbase + (long)sb * H);
    float2 hf[4];
    {
        __half2 v0 = hp2[lane * 2], v1 = hp2[lane * 2 + 1];
        __half2 v2 = hp2[64 + lane * 2], v3 = hp2[65 + lane * 2];
        hf[0] = __half22float2(v0); hf[1] = __half22float2(v1);
        hf[2] = __half22float2(v2); hf[3] = __half22float2(v3);
    }
    const float* wf = Wfcout + ss * 2 * H;
    float4 w0 = *(const float4*)&wf[lane * 4];
    float4 w1 = *(const float4*)&wf[128 + lane * 4];

    float red[T + 1];
    red[T] = hf[0].x * w0.x + hf[0].y * w0.y + hf[1].x * w0.z + hf[1].y * w0.w
           + hf[2].x * w1.x + hf[2].y * w1.y + hf[3].x * w1.z + hf[3].y * w1.w;
#pragma unroll
    for (int tt = 0; tt < T; tt++) {
        const __half2* kp2 = (const __half2*)(g_k2h + ((long)tt * S * B + sb) * H);
        float2 k0 = __half22float2(kp2[lane * 2]);
        float2 k1 = __half22float2(kp2[lane * 2 + 1]);
        float2 k2_ = __half22float2(kp2[64 + lane * 2]);
        float2 k3 = __half22float2(kp2[65 + lane * 2]);
        red[tt] = hf[0].x * k0.x + hf[0].y * k0.y + hf[1].x * k1.x + hf[1].y * k1.y
                + hf[2].x * k2_.x + hf[2].y * k2_.y + hf[3].x * k3.x + hf[3].y * k3.y;
    }
#pragma unroll
    for (int r = 0; r < T + 1; r++) {
        float v = red[r];
#pragma unroll
        for (int off = 16; off; off >>= 1) v += __shfl_xor_sync(0xffffffffu, v, off);
        red[r] = v;
    }
    float sc[T];
    float mx = -1e30f;
#pragma unroll
    for (int tt = 0; tt < T; tt++) {
        float v = (red[tt] + g_bqk[(long)tt * S * B + sb]) * 0.0625f;
        sc[tt] = v;
        mx = fmaxf(mx, v);
    }
    float sum = 0.f;
#pragma unroll
    for (int tt = 0; tt < T; tt++) { sc[tt] = __expf(sc[tt] - mx); sum += sc[tt]; }
    float inv = 1.f / sum;
    float ctxdot = 0.f;
#pragma unroll
    for (int tt = 0; tt < T; tt++)
        ctxdot = fmaf(sc[tt] * inv, g_vu[(long)tt * S * B + sb], ctxdot);
    if (lane == 0)
        g_outs[(long)lstep * S * B + sb] = red[T] + ctxdot + g_c1[ss];
}

// ============ persistent fp16 step kernel (enc: 12 steps / dec: 48+attn) ====
// 256 blocks x 256 thr, __launch_bounds__(256,2): regs<=128; smem 88KB -> 2/SM
// -> 296 slots >= 256 resident -> grid barrier safe.
// Per step: same single-wave body as R8 (A tile staged once, 2 j-halves).
template <int DEC>
__global__ void __launch_bounds__(256, 2) step16_p(
    const __half* __restrict__ h0in,
    __half* __restrict__ hApp, __half* __restrict__ hBpp,
    const __half* __restrict__ W16,
    const float* __restrict__ b1, const float* __restrict__ b2,
    const float* __restrict__ cvec,
    const __half* __restrict__ gin16,
    __half* __restrict__ enc16,
    const float* __restrict__ Wfcout)
{
    extern __shared__ __align__(16) __half smem[];
    __half* As = smem;                       // 128 * PA
    __half* Ws = smem + 128 * PA;            // 2 * 128 * PH

    const int bid = blockIdx.x;
    const int bx = bid & 3;
    const int m0 = ((bid >> 2) & 7) * 128;
    const int s  = bid >> 5;

    const int t = threadIdx.x;
    const int w = t >> 5, lane = t & 31;
    const int lq = lane >> 2, lr = lane & 3;
    const int wm = w & 3, wn = w >> 2;

    const int NSTEP = DEC ? (L + 1) : T;

#pragma unroll 1
    for (int it = 0; it < NSTEP; it++) {
        const __half* hin;
        if (DEC) hin = (it == 0) ? h0in : ((it & 1) ? hApp : hBpp);
        else     hin = (it == 0) ? h0in : (enc16 + (long)(it - 1) * SBH);

        if (!DEC || it < L) {
            __half* hout = DEC ? ((it & 1) ? hBpp : hApp) : (enc16 + (long)it * SBH);
            const __half* Aph = hin + ((long)s * B + m0) * H;

            auto issueW = [&](const __half* Wph, int cidx, int buf) {
#pragma unroll
                for (int p = 0; p < 2; p++) {
                    int idx = t + 256 * p;
                    int row = idx >> 2, seg = idx & 3;
                    cp16(&Ws[buf * 128 * PH + row * PH + seg * 8],
                         Wph + (long)row * H + cidx * 32 + seg * 8);
                }
            };

            {
#pragma unroll
                for (int p = 0; p < 16; p++) {
                    int idx = t + 256 * p;
                    int row = idx >> 5, seg = idx & 31;
                    cp16(&As[row * PA + seg * 8], Aph + (long)row * H + seg * 8);
                }
                const __half* Wph0 = W16 + ((long)(s * 8 + bx * 2) * 128) * H;
                issueW(Wph0, 0, 0);
                asm volatile("cp.async.commit_group;");
            }

#pragma unroll 1
            for (int hh = 0; hh < 2; hh++) {
                const int jblk = bx * 2 + hh;
                const __half* Wph = W16 + ((long)(s * 8 + jblk) * 128) * H;
                if (hh == 1) {
                    issueW(Wph, 0, 0);
                    asm volatile("cp.async.commit_group;");
                }

                float acc[2][8][4];
#pragma unroll
                for (int mt = 0; mt < 2; mt++)
#pragma unroll
                    for (int nt = 0; nt < 8; nt++)
#pragma unroll
                        for (int v = 0; v < 4; v++) acc[mt][nt][v] = 0.f;

#pragma unroll 1
                for (int c = 0; c < 8; c++) {
                    if (c < 7) {
                        issueW(Wph, c + 1, (c + 1) & 1);
                        asm volatile("cp.async.commit_group;");
                        asm volatile("cp.async.wait_group 1;");
                    } else {
                        asm volatile("cp.async.wait_group 0;");
                    }
                    __syncthreads();
                    int buf = c & 1;
                    const __half* Wsb = Ws + buf * 128 * PH;
#pragma unroll
                    for (int k16 = 0; k16 < 2; k16++) {
                        int ka = c * 32 + k16 * 16;
                        int kb = k16 * 16;
                        unsigned a[2][4];
#pragma unroll
                        for (int mt = 0; mt < 2; mt++) {
                            int r = wm * 32 + mt * 16 + lq;
                            a[mt][0] = *(const unsigned*)&As[r * PA + ka + lr * 2];
                            a[mt][1] = *(const unsigned*)&As[(r + 8) * PA + ka + lr * 2];
                            a[mt][2] = *(const unsigned*)&As[r * PA + ka + 8 + lr * 2];
                            a[mt][3] = *(const unsigned*)&As[(r + 8) * PA + ka + 8 + lr * 2];
                        }
#pragma unroll
                        for (int nt = 0; nt < 8; nt++) {
                            int rn = wn * 64 + nt * 8 + lq;
                            unsigned bb0 = *(const unsigned*)&Wsb[rn * PH + kb + lr * 2];
                            unsigned bb1 = *(const unsigned*)&Wsb[rn * PH + kb + 8 + lr * 2];
#pragma unroll
                            for (int mt = 0; mt < 2; mt++)
                                mma_f16(acc[mt][nt], a[mt][0], a[mt][1], a[mt][2], a[mt][3], bb0, bb1);
                        }
                    }
                    __syncthreads();
                }

                const int j0 = bx * 64 + hh * 32;
#pragma unroll
                for (int mt = 0; mt < 2; mt++) {
#pragma unroll
                    for (int rh = 0; rh < 2; rh++) {
                        int b_row = m0 + wm * 32 + mt * 16 + lq + rh * 8;
                        float rv = DEC ? g_inp[it * B + b_row] : 0.f;
#pragma unroll
                        for (int d = 0; d < 2; d++) {
                            int j = j0 + (wn * 2 + d) * 8 + lr * 2;
                            float gate[4][2];
#pragma unroll
                            for (int q = 0; q < 4; q++) {
                                int nt = d * 4 + q;
                                float v0 = acc[mt][nt][rh * 2];
                                float v1 = acc[mt][nt][rh * 2 + 1];
                                int gg = q * H + j;
                                if (DEC) {
                                    float2 x1 = *(const float2*)&b1[s * G + gg];
                                    float2 x2 = *(const float2*)&b2[s * G + gg];
                                    float2 xc = *(const float2*)&cvec[s * G + gg];
                                    v0 += x1.x + x2.x + rv * xc.x;
                                    v1 += x1.y + x2.y + rv * xc.y;
                                } else {
                                    __half2 xa = *(const __half2*)&gin16[
                                        (((long)(s * T + it)) * B + b_row) * G + gg];
                                    float2 xf = __half22float2(xa);
                                    v0 += xf.x; v1 += xf.y;
                                }
                                gate[q][0] = v0; gate[q][1] = v1;
                            }
                            long base = ((long)s * B + b_row) * H + j;
                            float2 cold = *(const float2*)&g_c[base];
                            float co[2] = {cold.x, cold.y};
                            float hn[2], cn[2];
#pragma unroll
                            for (int dd = 0; dd < 2; dd++) {
                                float c_ = sigf(gate[1][dd]) * co[dd]
                                         + sigf(gate[0][dd]) * tanhf(gate[2][dd]);
                                cn[dd] = c_;
                                hn[dd] = sigf(gate[3][dd]) * tanhf(c_);
                            }
                            *(float2*)&g_c[base] = make_float2(cn[0], cn[1]);
                            *(__half2*)&hout[base] = __floats2half2_rn(hn[0], hn[1]);
                        }
                    }
                }
            }
        }

        if (DEC && it >= 1) {
            int gw = bid * 8 + w;                 // 2048 warps
#pragma unroll 1
            for (int rep = 0; rep < 4; rep++)
                attn_one(hin, gw + rep * 2048, lane, Wfcout, it - 1);
        }

        if (it + 1 < NSTEP) grid_bar();
    }
}

// ---------------- per-(t,s,b) scalars (fp16 enc) ----------------
__global__ void pc_scal_kernel() {
    int gtid = blockIdx.x * blockDim.x + threadIdx.x;
    int warp = gtid >> 5;
    int lane = threadIdx.x & 31;
    if (warp >= T * S * B) return;
    int s = (warp >> 10) & 7;

    const __half2* ep = (const __half2*)(g_enc16 + (long)warp * H);
    const float* wb = g_wbqk + s * H;
    const float* wv = g_wvu + s * H;
    float db = 0.f, dv = 0.f;
#pragma unroll
    for (int u = 0; u < 2; u++) {
        int e = lane * 4 + u * 128;
        float2 e0 = __half22float2(ep[lane * 2 + u * 64]);
        float2 e1 = __half22float2(ep[lane * 2 + 1 + u * 64]);
        float4 b4 = *(const float4*)&wb[e];
        float4 v4 = *(const float4*)&wv[e];
        db += e0.x * b4.x + e0.y * b4.y + e1.x * b4.z + e1.y * b4.w;
        dv += e0.x * v4.x + e0.y * v4.y + e1.x * v4.z + e1.y * v4.w;
    }
#pragma unroll
    for (int off = 16; off; off >>= 1) {
        db += __shfl_xor_sync(0xffffffffu, db, off);
        dv += __shfl_xor_sync(0xffffffffu, dv, off);
    }
    if (lane == 0) {
        g_bqk[warp] = db + g_cbqk[s];
        g_vu[warp]  = dv + g_cvu[s];
    }
}

// ---------------- final 8->1 mix ----------------
__global__ void final_kernel(const float* __restrict__ Wfc, const float* __restrict__ bfc,
                             float* __restrict__ out) {
    int i = blockIdx.x * blockDim.x + threadIdx.x;
    if (i >= B * L) return;
    int b = i / L, l = i % L;
    float acc = bfc[0];
#pragma unroll
    for (int s = 0; s < S; s++)
        acc += g_outs[(long)l * S * B + (long)s * B + b] * Wfc[s];
    out[i] = acc;
}

// ---------------- host launch ----------------
extern "C" void kernel_launch(void* const* d_in, const int* in_sizes, int n_in,
                              void* d_out, int out_size) {
    const float* x       = (const float*)d_in[0];
    const float* tgt     = (const float*)d_in[1];
    const float* W_ih_e  = (const float*)d_in[2];
    const float* W_hh_e  = (const float*)d_in[3];
    const float* b_ih_e  = (const float*)d_in[4];
    const float* b_hh_e  = (const float*)d_in[5];
    const float* W_ih_d  = (const float*)d_in[6];
    const float* W_hh_d  = (const float*)d_in[7];
    const float* b_ih_d  = (const float*)d_in[8];
    const float* b_hh_d  = (const float*)d_in[9];
    const float* W_in    = (const float*)d_in[10];
    const float* b_in    = (const float*)d_in[11];
    const float* W_out   = (const float*)d_in[12];
    const float* b_out   = (const float*)d_in[13];
    const float* W_fcout = (const float*)d_in[14];
    const float* b_fcout = (const float*)d_in[15];
    const float* W_fc    = (const float*)d_in[16];
    const float* b_fc    = (const float*)d_in[17];
    float* out = (float*)d_out;

    __half *gin16, *x16, *w16ih, *enc16, *k2h, *hA, *hB, *W16e, *W16d, *M1h;
    float *k2b;
    cudaGetSymbolAddress((void**)&gin16, g_Gin16);
    cudaGetSymbolAddress((void**)&x16,   g_x16);
    cudaGetSymbolAddress((void**)&w16ih, g_W16ih);
    cudaGetSymbolAddress((void**)&enc16, g_enc16);
    cudaGetSymbolAddress((void**)&k2h,   g_k2h);
    cudaGetSymbolAddress((void**)&hA,    g_h16A);
    cudaGetSymbolAddress((void**)&hB,    g_h16B);
    cudaGetSymbolAddress((void**)&W16e,  g_W16e);
    cudaGetSymbolAddress((void**)&W16d,  g_W16d);
    cudaGetSymbolAddress((void**)&M1h,   g_M1h);
    cudaGetSymbolAddress((void**)&k2b,   g_k2b);

    static int smem_set = 0;
    if (!smem_set) {
        cudaFuncSetAttribute(step16_p<0>, cudaFuncAttributeMaxDynamicSharedMemorySize, STEP_SMEM);
        cudaFuncSetAttribute(step16_p<1>, cudaFuncAttributeMaxDynamicSharedMemorySize, STEP_SMEM);
        smem_set = 1;
    }

    prep_kernel<<<(SBH + 255) / 256, 256>>>(x, tgt);
    conv_w16<<<(int)((long)S * G * H / 256), 256>>>(W_hh_e, W16e);
    conv_w16<<<(int)((long)S * G * H / 256), 256>>>(W_hh_d, W16d);
    conv_x16<<<(int)(((long)B * 96 * KX + 255) / 256), 256>>>(x);
    conv_wih<<<(int)(((long)S * G * KX + 255) / 256), 256>>>(W_ih_e);
    pc_a<<<S * H * 32 / 256, 256>>>(W_out, W_fcout, W_in, b_in);
    pc_b<<<S * H * 32 / 256, 256>>>(W_in);
    pc_c<<<1, 256>>>(b_in, W_fcout, b_fcout, b_out);
    pc_m1<<<dim3(16, 16, 8), dim3(16, 16)>>>(W_in);

    // 1) encoder input projections (fp16 MMA, biases folded): Gin16[z=s*12+t]
    gemm_f16<<<dim3(G / 128, B / 128, 96), 256>>>(
        x16, (long)KX, 96 * KX,
        w16ih, (long)G * KX, KX,
        b_ih_e, b_hh_e, G,
        gin16, (long)B * G, G, KX / 32, 12);

    // 2) persistent encoder: 12 steps, 1 launch; h -> enc16[t]
    step16_p<0><<<NBP, 256, STEP_SMEM>>>(
        hA, nullptr, nullptr, W16e,
        nullptr, nullptr, nullptr,
        gin16, enc16, nullptr);

    // 3) per-key scalars + transformed keys (fp16 MMA)
    pc_scal_kernel<<<(T * S * B * 32 + 255) / 256, 256>>>();
    gemm_f16<<<dim3(H / 128, B / 128, T * S), 256>>>(
        enc16, (long)B * H, H,
        M1h, (long)H * H, H,
        k2b, nullptr, H,
        k2h, (long)B * H, H, H / 32, 1);

    // 4) persistent decoder: 48 steps + fused attention (incl. last), 1 launch
    step16_p<1><<<NBP, 256, STEP_SMEM>>>(
        enc16 + (long)11 * SBH, hA, hB, W16d,
        b_ih_d, b_hh_d, W_ih_d,
        nullptr, nullptr, W_fcout);

    // 5) final mix
    final_kernel<<<(B * L + 255) / 256, 256>>>(W_fc, b_fc, out);
}

// round 10
// speedup vs baseline: 2.2965x; 1.0845x over previous
#include <cuda_runtime.h>
#include <cuda_fp16.h>
#include <math.h>

// ---------------- problem constants ----------------
#define S   8
#define T   12
#define H   256
#define F   316
#define B   1024
#define L   48
#define G   1024      // 4*H
#define KX  320       // padded K for input projection
#define PH  40        // gemm_f16 smem pitch (halves), BK=32
#define PHW 72        // step Ws pitch (halves), BK=64
#define PA  264       // step A-full pitch (halves)
#define NBP 256       // persistent grid size
#define SBH (S * B * H)
#define STEP_SMEM (128 * PA * 2 + 2 * 128 * PHW * 2)   // 67584 + 36864 = 104448 B

// ---------------- scratch (device globals; no allocs allowed) ----------------
__device__ __half g_Gin16[96l * B * G];
__device__ __half g_x16[(long)B * 96 * KX];
__device__ __half g_W16ih[(long)S * G * KX];
__device__ __half g_enc16[(long)T * SBH];
__device__ __half g_k2h[(long)T * SBH];
__device__ __half g_h16A[SBH];
__device__ __half g_h16B[SBH];
__device__ __half g_W16e[(long)S * G * H];
__device__ __half g_W16d[(long)S * G * H];
__device__ __half g_M1h[S * H * H];
__device__ float  g_c  [SBH];
__device__ float  g_inp[L * B];
__device__ float  g_outs[(long)L * S * B];
__device__ float g_u    [S * H];
__device__ float g_wbqk [S * H];
__device__ float g_wvu  [S * H];
__device__ float g_k2b  [S * H];
__device__ float g_cbqk [S];
__device__ float g_cvu  [S];
__device__ float g_c1   [S];
__device__ float g_bqk  [(long)T * S * B];
__device__ float g_vu   [(long)T * S * B];
__device__ unsigned g_bar;

__device__ __forceinline__ float sigf(float x) { return 1.f / (1.f + __expf(-x)); }

__device__ __forceinline__ void mma_f16(float c[4],
    unsigned a0, unsigned a1, unsigned a2, unsigned a3,
    unsigned b0, unsigned b1)
{
    asm volatile(
        "mma.sync.aligned.m16n8k16.row.col.f32.f16.f16.f32 "
        "{%0,%1,%2,%3}, {%4,%5,%6,%7}, {%8,%9}, {%0,%1,%2,%3};"
        : "+f"(c[0]), "+f"(c[1]), "+f"(c[2]), "+f"(c[3])
        : "r"(a0), "r"(a1), "r"(a2), "r"(a3), "r"(b0), "r"(b1));
}

__device__ __forceinline__ void ldsm4(unsigned r[4], unsigned addr) {
    asm volatile("ldmatrix.sync.aligned.m8n8.x4.shared.b16 {%0,%1,%2,%3}, [%4];"
        : "=r"(r[0]), "=r"(r[1]), "=r"(r[2]), "=r"(r[3]) : "r"(addr));
}

__device__ __forceinline__ unsigned sptr(const void* p) {
    return (unsigned)__cvta_generic_to_shared(p);
}
__device__ __forceinline__ void cp16(void* s, const void* g) {
    asm volatile("cp.async.cg.shared.global [%0], [%1], 16;" :: "r"(sptr(s)), "l"(g));
}

// grid barrier (all NBP blocks resident by construction)
__device__ __forceinline__ void grid_bar() {
    __syncthreads();
    if (threadIdx.x == 0) {
        __threadfence();
        unsigned old = atomicAdd(&g_bar, 1u);
        unsigned gen = old >> 16;
        if ((old & 0xffffu) == NBP - 1)
            atomicAdd(&g_bar, 0x10000u - NBP);
        while ((*(volatile unsigned*)&g_bar) >> 16 == gen) __nanosleep(64);
        __threadfence();
    }
    __syncthreads();
}

// ---------------- prep & conversions ----------------
__global__ void prep_kernel(const float* __restrict__ x, const float* __restrict__ tgt) {
    int i = blockIdx.x * blockDim.x + threadIdx.x;
    if (i < SBH) { g_h16A[i] = __float2half(0.f); g_c[i] = 0.f; }
    if (i < L * B) {
        int l = i / B, b = i % B;
        g_inp[i] = (l == 0) ? x[(long)b * 96 * F + 95 * F + 0]
                            : tgt[(long)b * L + (l - 1)];
    }
}

// vectorized: 8 halves per thread (rows of F=316 floats are 16B aligned)
__global__ void conv_x16(const float* __restrict__ x) {
    long i = (long)blockIdx.x * 256 + threadIdx.x;
    long tot = (long)B * 96 * (KX / 8);
    if (i >= tot) return;
    int kq = (int)(i % (KX / 8));
    long br = i / (KX / 8);
    int k = kq * 8;
    const float* xp = x + br * F + k;
    float4 f0 = *(const float4*)xp;
    float4 f1 = (k + 4 < F) ? *(const float4*)(xp + 4) : make_float4(0.f, 0.f, 0.f, 0.f);
    __half2 h0 = __floats2half2_rn(f0.x, f0.y);
    __half2 h1 = __floats2half2_rn(f0.z, f0.w);
    __half2 h2 = __floats2half2_rn(f1.x, f1.y);
    __half2 h3 = __floats2half2_rn(f1.z, f1.w);
    uint4 u = make_uint4(*(unsigned*)&h0, *(unsigned*)&h1, *(unsigned*)&h2, *(unsigned*)&h3);
    *(uint4*)(g_x16 + br * KX + k) = u;
}

__global__ void conv_wih(const float* __restrict__ Wf) {
    long i = (long)blockIdx.x * 256 + threadIdx.x;
    long tot = (long)S * G * (KX / 8);
    if (i >= tot) return;
    int kq = (int)(i % (KX / 8));
    long sg = i / (KX / 8);
    int k = kq * 8;
    const float* wp = Wf + sg * F + k;
    float4 f0 = *(const float4*)wp;
    float4 f1 = (k + 4 < F) ? *(const float4*)(wp + 4) : make_float4(0.f, 0.f, 0.f, 0.f);
    __half2 h0 = __floats2half2_rn(f0.x, f0.y);
    __half2 h1 = __floats2half2_rn(f0.z, f0.w);
    __half2 h2 = __floats2half2_rn(f1.x, f1.y);
    __half2 h3 = __floats2half2_rn(f1.z, f1.w);
    uint4 u = make_uint4(*(unsigned*)&h0, *(unsigned*)&h1, *(unsigned*)&h2, *(unsigned*)&h3);
    *(uint4*)(g_W16ih + sg * KX + k) = u;
}

// W_hh f32 [s][4H][H] -> fp16 gate-interleaved [s][jblk][128][256]
__global__ void conv_w16(const float* __restrict__ W, __half* __restrict__ dst) {
    long i = (long)blockIdx.x * 256 + threadIdx.x;
    int k = i & 255;
    long rr = i >> 8;
    int r = rr & 127;
    long jj_ = rr >> 7;
    int jb = jj_ & 7;
    int s = (int)(jj_ >> 3);
    int q = (r >> 3) & 3;
    int jloc = (r & 7) + ((r >> 5) << 3);
    dst[i] = __float2half(W[(long)s * G * H + (q * H + jb * 32 + jloc) * (long)H + k]);
}

// ---------------- warp-parallel precomputes ----------------
__global__ void pc_a(const float* __restrict__ Wout, const float* __restrict__ Wfcout,
                     const float* __restrict__ Win,  const float* __restrict__ b_in) {
    int gw = (blockIdx.x * blockDim.x + threadIdx.x) >> 5;
    int lane = threadIdx.x & 31;
    if (gw >= S * H) return;
    int s = gw >> 8, e = gw & 255;
    const float* wf2 = Wfcout + s * 2 * H + H;
    const float* Wo  = Wout + (long)s * H * H;
    const float* bq = b_in + s * 3 * H;
    const float* bk = bq + H;
    const float* Wq = Win + (long)s * 3 * H * H;
    const float* Wk = Wq + H * H;
    float u = 0.f, wb = 0.f, kb = 0.f;
#pragma unroll
    for (int i = 0; i < 8; i++) {
        int o = lane + i * 32;
        u  += wf2[o] * Wo[o * H + e];
        wb += bq[o]  * Wk[o * H + e];
        kb += Wq[o * H + e] * bk[o];
    }
#pragma unroll
    for (int off = 16; off; off >>= 1) {
        u  += __shfl_xor_sync(0xffffffffu, u, off);
        wb += __shfl_xor_sync(0xffffffffu, wb, off);
        kb += __shfl_xor_sync(0xffffffffu, kb, off);
    }
    if (lane == 0) { g_u[gw] = u; g_wbqk[gw] = wb; g_k2b[gw] = kb; }
}

__global__ void pc_b(const float* __restrict__ Win) {
    int gw = (blockIdx.x * blockDim.x + threadIdx.x) >> 5;
    int lane = threadIdx.x & 31;
    if (gw >= S * H) return;
    int s = gw >> 8, h = gw & 255;
    const float* Wv = Win + (long)s * 3 * H * H + 2 * H * H;
    float wv = 0.f;
#pragma unroll
    for (int i = 0; i < 8; i++) {
        int e = lane + i * 32;
        wv += g_u[s * H + e] * Wv[e * H + h];
    }
#pragma unroll
    for (int off = 16; off; off >>= 1) wv += __shfl_xor_sync(0xffffffffu, wv, off);
    if (lane == 0) g_wvu[gw] = wv;
}

__global__ void pc_c(const float* __restrict__ b_in, const float* __restrict__ Wfcout,
                     const float* __restrict__ b_fcout, const float* __restrict__ b_out) {
    int s = threadIdx.x >> 5;
    int lane = threadIdx.x & 31;
    if (s >= S) return;
    const float* bq = b_in + s * 3 * H;
    const float* bk = bq + H;
    const float* bv = bq + 2 * H;
    const float* wf2 = Wfcout + s * 2 * H + H;
    const float* bo  = b_out + s * H;
    float cvu = 0.f, cb = 0.f, c1 = 0.f;
#pragma unroll
    for (int i = 0; i < 8; i++) {
        int e = lane + i * 32;
        cvu += g_u[s * H + e] * bv[e];
        cb  += bq[e] * bk[e];
        c1  += wf2[e] * bo[e];
    }
#pragma unroll
    for (int off = 16; off; off >>= 1) {
        cvu += __shfl_xor_sync(0xffffffffu, cvu, off);
        cb  += __shfl_xor_sync(0xffffffffu, cb, off);
        c1  += __shfl_xor_sync(0xffffffffu, c1, off);
    }
    if (lane == 0) { g_cvu[s] = cvu; g_cbqk[s] = cb; g_c1[s] = c1 + b_fcout[s]; }
}

__global__ void pc_m1(const float* __restrict__ Win) {
    __shared__ float tq[16][17];
    __shared__ float tk[16][17];
    int s = blockIdx.z;
    const float* Wq = Win + (long)s * 3 * H * H;
    const float* Wk = Wq + H * H;
    int tyy = threadIdx.y, txx = threadIdx.x;
    int hq = blockIdx.y * 16 + tyy;
    int hk = blockIdx.x * 16 + txx;
    float acc = 0.f;
    for (int e0 = 0; e0 < H; e0 += 16) {
        tq[tyy][txx] = Wq[(e0 + tyy) * H + blockIdx.y * 16 + txx];
        tk[tyy][txx] = Wk[(e0 + tyy) * H + hk];
        __syncthreads();
#pragma unroll
        for (int ee = 0; ee < 16; ee++)
            acc = fmaf(tq[ee][tyy], tk[ee][txx], acc);
        __syncthreads();
    }
    g_M1h[(long)s * H * H + hq * H + hk] = __float2half(acc);
}

// ================= generic fp16 tensor-core GEMM (ldmatrix) =================
__global__ void __launch_bounds__(256) gemm_f16(
    const __half* __restrict__ Ag, long sAz, int lda,
    const __half* __restrict__ Wg, long sWz, int ldw,
    const float* __restrict__ b1, const float* __restrict__ b2, long sBz,
    __half* __restrict__ C, long sCz, int ldc,
    int NC, int wdiv)
{
    __shared__ __align__(16) __half As[2][128 * PH];
    __shared__ __align__(16) __half Ws[2][128 * PH];

    const int z  = blockIdx.z;
    const int wi = (z / wdiv) & 7;
    const int m0 = blockIdx.y * 128;
    const int n0 = blockIdx.x * 128;

    const __half* Ap = Ag + (long)z * sAz + (long)m0 * lda;
    const __half* Wp = Wg + (long)wi * sWz + (long)n0 * ldw;

    const int t = threadIdx.x;
    const int w = t >> 5, lane = t & 31;
    const int lq = lane >> 2, lr = lane & 3;
    const int wm = w & 3, wn = w >> 2;

    const unsigned as_b = sptr(&As[0][0]);
    const unsigned ws_b = sptr(&Ws[0][0]);
    const int a_row = wm * 32 + (lane & 15);
    const int a_k8  = (lane >> 4) << 3;
    const unsigned aoff0 = (unsigned)((a_row * PH + a_k8) * 2);
    const unsigned aoff1 = (unsigned)(((a_row + 16) * PH + a_k8) * 2);
    const int b_row = wn * 64 + (lane & 7) + ((lane >> 4) << 3);
    const int b_k8  = ((lane >> 3) & 1) << 3;
    const unsigned boff = (unsigned)((b_row * PH + b_k8) * 2);

    auto issue = [&](int c) {
        int buf = c & 1;
#pragma unroll
        for (int p = 0; p < 2; p++) {
            int idx = t + 256 * p;
            int row = idx >> 2, seg = idx & 3;
            cp16(&As[buf][row * PH + seg * 8], Ap + (long)row * lda + c * 32 + seg * 8);
            cp16(&Ws[buf][row * PH + seg * 8], Wp + (long)row * ldw + c * 32 + seg * 8);
        }
        asm volatile("cp.async.commit_group;");
    };

    float acc[2][8][4];
#pragma unroll
    for (int mt = 0; mt < 2; mt++)
#pragma unroll
        for (int nt = 0; nt < 8; nt++)
#pragma unroll
            for (int v = 0; v < 4; v++) acc[mt][nt][v] = 0.f;

    issue(0);

#pragma unroll 1
    for (int c = 0; c < NC; c++) {
        if (c < NC - 1) {
            issue(c + 1);
            asm volatile("cp.async.wait_group 1;");
        } else {
            asm volatile("cp.async.wait_group 0;");
        }
        __syncthreads();
        int buf = c & 1;
        unsigned ab = as_b + buf * (128 * PH * 2);
        unsigned wbb = ws_b + buf * (128 * PH * 2);
#pragma unroll
        for (int k16 = 0; k16 < 2; k16++) {
            int kb = k16 * 16;
            unsigned a0[4], a1[4];
            ldsm4(a0, ab + aoff0 + kb * 2);
            ldsm4(a1, ab + aoff1 + kb * 2);
#pragma unroll
            for (int bq = 0; bq < 4; bq++) {
                unsigned bb[4];
                ldsm4(bb, wbb + boff + (bq * 16 * PH + kb) * 2);
                mma_f16(acc[0][bq * 2],     a0[0], a0[1], a0[2], a0[3], bb[0], bb[1]);
                mma_f16(acc[1][bq * 2],     a1[0], a1[1], a1[2], a1[3], bb[0], bb[1]);
                mma_f16(acc[0][bq * 2 + 1], a0[0], a0[1], a0[2], a0[3], bb[2], bb[3]);
                mma_f16(acc[1][bq * 2 + 1], a1[0], a1[1], a1[2], a1[3], bb[2], bb[3]);
            }
        }
        __syncthreads();
    }

#pragma unroll
    for (int mt = 0; mt < 2; mt++) {
#pragma unroll
        for (int nt = 0; nt < 8; nt++) {
#pragma unroll
            for (int rh = 0; rh < 2; rh++) {
                int m = m0 + wm * 32 + mt * 16 + lq + rh * 8;
                int n = n0 + wn * 64 + nt * 8 + lr * 2;
                float v0 = acc[mt][nt][rh * 2];
                float v1 = acc[mt][nt][rh * 2 + 1];
                if (b1) { v0 += b1[(long)wi * sBz + n]; v1 += b1[(long)wi * sBz + n + 1]; }
                if (b2) { v0 += b2[(long)wi * sBz + n]; v1 += b2[(long)wi * sBz + n + 1]; }
                *(__half2*)&C[(long)z * sCz + (long)m * ldc + n] = __floats2half2_rn(v0, v1);
            }
        }
    }
}

// ---------------- shared attention device function ----------------
__device__ __forceinline__ void attn_one(const __half* __restrict__ hbase, int sb, int lane,
                                         const float* __restrict__ Wfcout, int lstep)
{
    int ss = sb >> 10;
    const __half2* hp2 = (const __half2*)(hbase + (long)sb * H);
    float2 hf[4];
    {
        __half2 v0 = hp2[lane * 2], v1 = hp2[lane * 2 + 1];
        __half2 v2 = hp2[64 + lane * 2], v3 = hp2[65 + lane * 2];
        hf[0] = __half22float2(v0); hf[1] = __half22float2(v1);
        hf[2] = __half22float2(v2); hf[3] = __half22float2(v3);
    }
    const float* wf = Wfcout + ss * 2 * H;
    float4 w0 = *(const float4*)&wf[lane * 4];
    float4 w1 = *(const float4*)&wf[128 + lane * 4];

    float red[T + 1];
    red[T] = hf[0].x * w0.x + hf[0].y * w0.y + hf[1].x * w0.z + hf[1].y * w0.w
           + hf[2].x * w1.x + hf[2].y * w1.y + hf[3].x * w1.z + hf[3].y * w1.w;
#pragma unroll
    for (int tt = 0; tt < T; tt++) {
        const __half2* kp2 = (const __half2*)(g_k2h + ((long)tt * S * B + sb) * H);
        float2 k0 = __half22float2(kp2[lane * 2]);
        float2 k1 = __half22float2(kp2[lane * 2 + 1]);
        float2 k2_ = __half22float2(kp2[64 + lane * 2]);
        float2 k3 = __half22float2(kp2[65 + lane * 2]);
        red[tt] = hf[0].x * k0.x + hf[0].y * k0.y + hf[1].x * k1.x + hf[1].y * k1.y
                + hf[2].x * k2_.x + hf[2].y * k2_.y + hf[3].x * k3.x + hf[3].y * k3.y;
    }
#pragma unroll
    for (int r = 0; r < T + 1; r++) {
        float v = red[r];
#pragma unroll
        for (int off = 16; off; off >>= 1) v += __shfl_xor_sync(0xffffffffu, v, off);
        red[r] = v;
    }
    float sc[T];
    float mx = -1e30f;
#pragma unroll
    for (int tt = 0; tt < T; tt++) {
        float v = (red[tt] + g_bqk[(long)tt * S * B + sb]) * 0.0625f;
        sc[tt] = v;
        mx = fmaxf(mx, v);
    }
    float sum = 0.f;
#pragma unroll
    for (int tt = 0; tt < T; tt++) { sc[tt] = __expf(sc[tt] - mx); sum += sc[tt]; }
    float inv = 1.f / sum;
    float ctxdot = 0.f;
#pragma unroll
    for (int tt = 0; tt < T; tt++)
        ctxdot = fmaf(sc[tt] * inv, g_vu[(long)tt * S * B + sb], ctxdot);
    if (lane == 0)
        g_outs[(long)lstep * S * B + sb] = red[T] + ctxdot + g_c1[ss];
}

// ============ persistent fp16 step kernel (ldmatrix, BK=64) =================
template <int DEC>
__global__ void __launch_bounds__(256, 2) step16_p(
    const __half* __restrict__ h0in,
    __half* __restrict__ hApp, __half* __restrict__ hBpp,
    const __half* __restrict__ W16,
    const float* __restrict__ b1, const float* __restrict__ b2,
    const float* __restrict__ cvec,
    const __half* __restrict__ gin16,
    __half* __restrict__ enc16,
    const float* __restrict__ Wfcout)
{
    extern __shared__ __align__(16) __half smem[];
    __half* As = smem;                       // 128 * PA
    __half* Ws = smem + 128 * PA;            // 2 * 128 * PHW

    const int bid = blockIdx.x;
    const int bx = bid & 3;
    const int m0 = ((bid >> 2) & 7) * 128;
    const int s  = bid >> 5;

    const int t = threadIdx.x;
    const int w = t >> 5, lane = t & 31;
    const int lq = lane >> 2, lr = lane & 3;
    const int wm = w & 3, wn = w >> 2;

    const unsigned as_b = sptr(As);
    const unsigned ws_b = sptr(Ws);
    const int a_row = wm * 32 + (lane & 15);
    const int a_k8  = (lane >> 4) << 3;
    const unsigned aoff0 = (unsigned)((a_row * PA + a_k8) * 2);
    const unsigned aoff1 = (unsigned)(((a_row + 16) * PA + a_k8) * 2);
    const int b_row = wn * 64 + (lane & 7) + ((lane >> 4) << 3);
    const int b_k8  = ((lane >> 3) & 1) << 3;
    const unsigned boff = (unsigned)((b_row * PHW + b_k8) * 2);

    const int NSTEP = DEC ? (L + 1) : T;

#pragma unroll 1
    for (int it = 0; it < NSTEP; it++) {
        const __half* hin;
        if (DEC) hin = (it == 0) ? h0in : ((it & 1) ? hApp : hBpp);
        else     hin = (it == 0) ? h0in : (enc16 + (long)(it - 1) * SBH);

        if (!DEC || it < L) {
            __half* hout = DEC ? ((it & 1) ? hBpp : hApp) : (enc16 + (long)it * SBH);
            const __half* Aph = hin + ((long)s * B + m0) * H;

            auto issueW = [&](const __half* Wph, int cidx, int buf) {
#pragma unroll
                for (int p = 0; p < 4; p++) {
                    int idx = t + 256 * p;
                    int row = idx >> 3, seg = idx & 7;
                    cp16(&Ws[buf * 128 * PHW + row * PHW + seg * 8],
                         Wph + (long)row * H + cidx * 64 + seg * 8);
                }
            };

            {
#pragma unroll
                for (int p = 0; p < 16; p++) {
                    int idx = t + 256 * p;
                    int row = idx >> 5, seg = idx & 31;
                    cp16(&As[row * PA + seg * 8], Aph + (long)row * H + seg * 8);
                }
                const __half* Wph0 = W16 + ((long)(s * 8 + bx * 2) * 128) * H;
                issueW(Wph0, 0, 0);
                asm volatile("cp.async.commit_group;");
            }

#pragma unroll 1
            for (int hh = 0; hh < 2; hh++) {
                const int jblk = bx * 2 + hh;
                const __half* Wph = W16 + ((long)(s * 8 + jblk) * 128) * H;
                if (hh == 1) {
                    issueW(Wph, 0, 0);
                    asm volatile("cp.async.commit_group;");
                }

                float acc[2][8][4];
#pragma unroll
                for (int mt = 0; mt < 2; mt++)
#pragma unroll
                    for (int nt = 0; nt < 8; nt++)
#pragma unroll
                        for (int v = 0; v < 4; v++) acc[mt][nt][v] = 0.f;

#pragma unroll 1
                for (int c = 0; c < 4; c++) {
                    if (c < 3) {
                        issueW(Wph, c + 1, (c + 1) & 1);
                        asm volatile("cp.async.commit_group;");
                        asm volatile("cp.async.wait_group 1;");
                    } else {
                        asm volatile("cp.async.wait_group 0;");
                    }
                    __syncthreads();
                    int buf = c & 1;
                    unsigned wsbuf = ws_b + buf * (128 * PHW * 2);
#pragma unroll
                    for (int k16 = 0; k16 < 4; k16++) {
                        int ka = c * 64 + k16 * 16;
                        int kb = k16 * 16;
                        unsigned a0[4], a1[4];
                        ldsm4(a0, as_b + aoff0 + ka * 2);
                        ldsm4(a1, as_b + aoff1 + ka * 2);
#pragma unroll
                        for (int bq = 0; bq < 4; bq++) {
                            unsigned bb[4];
                            ldsm4(bb, wsbuf + boff + (bq * 16 * PHW + kb) * 2);
                            mma_f16(acc[0][bq * 2],     a0[0], a0[1], a0[2], a0[3], bb[0], bb[1]);
                            mma_f16(acc[1][bq * 2],     a1[0], a1[1], a1[2], a1[3], bb[0], bb[1]);
                            mma_f16(acc[0][bq * 2 + 1], a0[0], a0[1], a0[2], a0[3], bb[2], bb[3]);
                            mma_f16(acc[1][bq * 2 + 1], a1[0], a1[1], a1[2], a1[3], bb[2], bb[3]);
                        }
                    }
                    __syncthreads();
                }

                const int j0 = bx * 64 + hh * 32;
#pragma unroll
                for (int mt = 0; mt < 2; mt++) {
#pragma unroll
                    for (int rh = 0; rh < 2; rh++) {
                        int b_row2 = m0 + wm * 32 + mt * 16 + lq + rh * 8;
                        float rv = DEC ? g_inp[it * B + b_row2] : 0.f;
#pragma unroll
                        for (int d = 0; d < 2; d++) {
                            int j = j0 + (wn * 2 + d) * 8 + lr * 2;
                            float gate[4][2];
#pragma unroll
                            for (int q = 0; q < 4; q++) {
                                int nt = d * 4 + q;
                                float v0 = acc[mt][nt][rh * 2];
                                float v1 = acc[mt][nt][rh * 2 + 1];
                                int gg = q * H + j;
                                if (DEC) {
                                    float2 x1 = *(const float2*)&b1[s * G + gg];
                                    float2 x2 = *(const float2*)&b2[s * G + gg];
                                    float2 xc = *(const float2*)&cvec[s * G + gg];
                                    v0 += x1.x + x2.x + rv * xc.x;
                                    v1 += x1.y + x2.y + rv * xc.y;
                                } else {
                                    __half2 xa = *(const __half2*)&gin16[
                                        (((long)(s * T + it)) * B + b_row2) * G + gg];
                                    float2 xf = __half22float2(xa);
                                    v0 += xf.x; v1 += xf.y;
                                }
                                gate[q][0] = v0; gate[q][1] = v1;
                            }
                            long base = ((long)s * B + b_row2) * H + j;
                            float2 cold = *(const float2*)&g_c[base];
                            float co[2] = {cold.x, cold.y};
                            float hn[2], cn[2];
#pragma unroll
                            for (int dd = 0; dd < 2; dd++) {
                                float c_ = sigf(gate[1][dd]) * co[dd]
                                         + sigf(gate[0][dd]) * tanhf(gate[2][dd]);
                                cn[dd] = c_;
                                hn[dd] = sigf(gate[3][dd]) * tanhf(c_);
                            }
                            *(float2*)&g_c[base] = make_float2(cn[0], cn[1]);
                            *(__half2*)&hout[base] = __floats2half2_rn(hn[0], hn[1]);
                        }
                    }
                }
            }
        }

        if (DEC && it >= 1) {
            int gw = bid * 8 + w;
#pragma unroll 1
            for (int rep = 0; rep < 4; rep++)
                attn_one(hin, gw + rep * 2048, lane, Wfcout, it - 1);
        }

        if (it + 1 < NSTEP) grid_bar();
    }
}

// ---------------- per-(t,s,b) scalars ----------------
__global__ void pc_scal_kernel() {
    int gtid = blockIdx.x * blockDim.x + threadIdx.x;
    int warp = gtid >> 5;
    int lane = threadIdx.x & 31;
    if (warp >= T * S * B) return;
    int s = (warp >> 10) & 7;

    const __half2* ep = (const __half2*)(g_enc16 + (long)warp * H);
    const float* wb = g_wbqk + s * H;
    const float* wv = g_wvu + s * H;
    float db = 0.f, dv = 0.f;
#pragma unroll
    for (int u = 0; u < 2; u++) {
        int e = lane * 4 + u * 128;
        float2 e0 = __half22float2(ep[lane * 2 + u * 64]);
        float2 e1 = __half22float2(ep[lane * 2 + 1 + u * 64]);
        float4 b4 = *(const float4*)&wb[e];
        float4 v4 = *(const float4*)&wv[e];
        db += e0.x * b4.x + e0.y * b4.y + e1.x * b4.z + e1.y * b4.w;
        dv += e0.x * v4.x + e0.y * v4.y + e1.x * v4.z + e1.y * v4.w;
    }
#pragma unroll
    for (int off = 16; off; off >>= 1) {
        db += __shfl_xor_sync(0xffffffffu, db, off);
        dv += __shfl_xor_sync(0xffffffffu, dv, off);
    }
    if (lane == 0) {
        g_bqk[warp] = db + g_cbqk[s];
        g_vu[warp]  = dv + g_cvu[s];
    }
}

// ---------------- final 8->1 mix ----------------
__global__ void final_kernel(const float* __restrict__ Wfc, const float* __restrict__ bfc,
                             float* __restrict__ out) {
    int i = blockIdx.x * blockDim.x + threadIdx.x;
    if (i >= B * L) return;
    int b = i / L, l = i % L;
    float acc = bfc[0];
#pragma unroll
    for (int s = 0; s < S; s++)
        acc += g_outs[(long)l * S * B + (long)s * B + b] * Wfc[s];
    out[i] = acc;
}

// ---------------- host launch ----------------
extern "C" void kernel_launch(void* const* d_in, const int* in_sizes, int n_in,
                              void* d_out, int out_size) {
    const float* x       = (const float*)d_in[0];
    const float* tgt     = (const float*)d_in[1];
    const float* W_ih_e  = (const float*)d_in[2];
    const float* W_hh_e  = (const float*)d_in[3];
    const float* b_ih_e  = (const float*)d_in[4];
    const float* b_hh_e  = (const float*)d_in[5];
    const float* W_ih_d  = (const float*)d_in[6];
    const float* W_hh_d  = (const float*)d_in[7];
    const float* b_ih_d  = (const float*)d_in[8];
    const float* b_hh_d  = (const float*)d_in[9];
    const float* W_in    = (const float*)d_in[10];
    const float* b_in    = (const float*)d_in[11];
    const float* W_out   = (const float*)d_in[12];
    const float* b_out   = (const float*)d_in[13];
    const float* W_fcout = (const float*)d_in[14];
    const float* b_fcout = (const float*)d_in[15];
    const float* W_fc    = (const float*)d_in[16];
    const float* b_fc    = (const float*)d_in[17];
    float* out = (float*)d_out;

    __half *gin16, *x16, *w16ih, *enc16, *k2h, *hA, *hB, *W16e, *W16d, *M1h;
    float *k2b;
    cudaGetSymbolAddress((void**)&gin16, g_Gin16);
    cudaGetSymbolAddress((void**)&x16,   g_x16);
    cudaGetSymbolAddress((void**)&w16ih, g_W16ih);
    cudaGetSymbolAddress((void**)&enc16, g_enc16);
    cudaGetSymbolAddress((void**)&k2h,   g_k2h);
    cudaGetSymbolAddress((void**)&hA,    g_h16A);
    cudaGetSymbolAddress((void**)&hB,    g_h16B);
    cudaGetSymbolAddress((void**)&W16e,  g_W16e);
    cudaGetSymbolAddress((void**)&W16d,  g_W16d);
    cudaGetSymbolAddress((void**)&M1h,   g_M1h);
    cudaGetSymbolAddress((void**)&k2b,   g_k2b);

    static int smem_set = 0;
    if (!smem_set) {
        cudaFuncSetAttribute(step16_p<0>, cudaFuncAttributeMaxDynamicSharedMemorySize, STEP_SMEM);
        cudaFuncSetAttribute(step16_p<1>, cudaFuncAttributeMaxDynamicSharedMemorySize, STEP_SMEM);
        smem_set = 1;
    }

    prep_kernel<<<(SBH + 255) / 256, 256>>>(x, tgt);
    conv_w16<<<(int)((long)S * G * H / 256), 256>>>(W_hh_e, W16e);
    conv_w16<<<(int)((long)S * G * H / 256), 256>>>(W_hh_d, W16d);
    conv_x16<<<(int)(((long)B * 96 * (KX / 8) + 255) / 256), 256>>>(x);
    conv_wih<<<(int)(((long)S * G * (KX / 8) + 255) / 256), 256>>>(W_ih_e);
    pc_a<<<S * H * 32 / 256, 256>>>(W_out, W_fcout, W_in, b_in);
    pc_b<<<S * H * 32 / 256, 256>>>(W_in);
    pc_c<<<1, 256>>>(b_in, W_fcout, b_fcout, b_out);
    pc_m1<<<dim3(16, 16, 8), dim3(16, 16)>>>(W_in);

    // 1) encoder input projections (fp16 MMA): Gin16[z=s*12+t]
    gemm_f16<<<dim3(G / 128, B / 128, 96), 256>>>(
        x16, (long)KX, 96 * KX,
        w16ih, (long)G * KX, KX,
        b_ih_e, b_hh_e, G,
        gin16, (long)B * G, G, KX / 32, 12);

    // 2) persistent encoder
    step16_p<0><<<NBP, 256, STEP_SMEM>>>(
        hA, nullptr, nullptr, W16e,
        nullptr, nullptr, nullptr,
        gin16, enc16, nullptr);

    // 3) per-key scalars + transformed keys
    pc_scal_kernel<<<(T * S * B * 32 + 255) / 256, 256>>>();
    gemm_f16<<<dim3(H / 128, B / 128, T * S), 256>>>(
        enc16, (long)B * H, H,
        M1h, (long)H * H, H,
        k2b, nullptr, H,
        k2h, (long)B * H, H, H / 32, 1);

    // 4) persistent decoder (48 steps + fused attention)
    step16_p<1><<<NBP, 256, STEP_SMEM>>>(
        enc16 + (long)11 * SBH, hA, hB, W16d,
        b_ih_d, b_hh_d, W_ih_d,
        nullptr, nullptr, W_fcout);

    // 5) final mix
    final_kernel<<<(B * L + 255) / 256, 256>>>(W_fc, b_fc, out);
}